// round 1
// baseline (speedup 1.0000x reference)
#include <cuda_runtime.h>
#include <math.h>

// Problem constants (fixed by the dataset)
#define BS    2
#define SLEN  2048
#define EMB   1024
#define NHD   1024   // NH*DM
#define NH    16
#define DM    64
#define MROWS (BS * SLEN)   // 4096

// ---------------- scratch (no allocation allowed) ----------------
__device__ float g_q [MROWS * NHD];
__device__ float g_k [MROWS * NHD];
__device__ float g_v [MROWS * NHD];
__device__ float g_ao[MROWS * NHD];

// ---------------- SGEMM: C = alpha * (A[M,K] @ B[K,N] + bias[N]) ----------------
// BM=BN=128, BK=8, 256 threads, 8x8 per-thread microtile.
__global__ __launch_bounds__(256) void sgemm_bias(
    const float* __restrict__ A, const float* __restrict__ B,
    const float* __restrict__ bias, float* __restrict__ C,
    int M, int N, int K, float alpha)
{
    __shared__ float As[8][128];
    __shared__ float Bs[8][128];

    const int tid = threadIdx.x;
    const int bm = blockIdx.y * 128;
    const int bn = blockIdx.x * 128;

    const int arow = tid >> 1;          // 0..127
    const int acol = (tid & 1) << 2;    // 0 or 4
    const int brow = tid >> 5;          // 0..7
    const int bcol = (tid & 31) << 2;   // 0..124

    const int tx = tid & 15;            // col group
    const int ty = tid >> 4;            // row group

    float acc[8][8];
    #pragma unroll
    for (int i = 0; i < 8; ++i)
        #pragma unroll
        for (int j = 0; j < 8; ++j) acc[i][j] = 0.f;

    const float* Aptr = A + (size_t)(bm + arow) * K + acol;
    const float* Bptr = B + (size_t)brow * N + bn + bcol;

    for (int k0 = 0; k0 < K; k0 += 8) {
        float4 av = *(const float4*)(Aptr + k0);
        float4 bv = *(const float4*)(Bptr + (size_t)k0 * N);

        As[acol + 0][arow] = av.x;
        As[acol + 1][arow] = av.y;
        As[acol + 2][arow] = av.z;
        As[acol + 3][arow] = av.w;
        *(float4*)&Bs[brow][bcol] = bv;
        __syncthreads();

        #pragma unroll
        for (int kk = 0; kk < 8; ++kk) {
            float a[8], b[8];
            *(float4*)(a + 0) = *(const float4*)&As[kk][ty * 8 + 0];
            *(float4*)(a + 4) = *(const float4*)&As[kk][ty * 8 + 4];
            *(float4*)(b + 0) = *(const float4*)&Bs[kk][tx * 8 + 0];
            *(float4*)(b + 4) = *(const float4*)&Bs[kk][tx * 8 + 4];
            #pragma unroll
            for (int i = 0; i < 8; ++i)
                #pragma unroll
                for (int j = 0; j < 8; ++j)
                    acc[i][j] = fmaf(a[i], b[j], acc[i][j]);
        }
        __syncthreads();
    }

    // epilogue: alpha * (acc + bias)
    #pragma unroll
    for (int i = 0; i < 8; ++i) {
        const int row = bm + ty * 8 + i;
        float* crow = C + (size_t)row * N + bn + tx * 8;
        #pragma unroll
        for (int j4 = 0; j4 < 8; j4 += 4) {
            const int col = bn + tx * 8 + j4;
            float4 ov;
            ov.x = alpha * (acc[i][j4 + 0] + bias[col + 0]);
            ov.y = alpha * (acc[i][j4 + 1] + bias[col + 1]);
            ov.z = alpha * (acc[i][j4 + 2] + bias[col + 2]);
            ov.w = alpha * (acc[i][j4 + 3] + bias[col + 3]);
            *(float4*)(crow + j4) = ov;
        }
    }
}

// ---------------- Flash attention (fp32, BM=BN=64, D=64) ----------------
// grid: (SLEN/64, NH, BS), 256 threads (tx 0..15 cols, ty 0..15 rows), 4x4 microtile.
// q is pre-scaled by 1/sqrt(DM) (folded into the Q projection).
__global__ __launch_bounds__(256) void flash_attn(
    const float* __restrict__ q, const float* __restrict__ k,
    const float* __restrict__ v, float* __restrict__ o)
{
    extern __shared__ float sm[];
    float* Qs = sm;            // [64][64] transposed: Qs[d*64 + i]
    float* Ks = sm + 4096;     // [64][64] transposed: Ks[d*64 + j]
    float* Vs = sm + 8192;     // [64][64] row-major:  Vs[j*64 + d]
    float* Ps = sm + 12288;    // [64][65] padded

    const int tid = threadIdx.x;
    const int tx = tid & 15;
    const int ty = tid >> 4;
    const int h = blockIdx.y, b = blockIdx.z;
    const int i0 = blockIdx.x * 64;

    const size_t base = (size_t)b * SLEN * NHD + (size_t)h * DM;
    const float* qb = q + base;
    const float* kb = k + base;
    const float* vb = v + base;
    float*       ob = o + base;

    // Load Q tile (64 rows x 64 cols), transposed into Qs[d][i]
    #pragma unroll
    for (int rep = 0; rep < 4; ++rep) {
        int idx = tid + rep * 256;     // 0..1023
        int row = idx >> 4;            // 0..63
        int c4  = (idx & 15) << 2;     // 0..60 step 4
        float4 t = *(const float4*)(qb + (size_t)(i0 + row) * NHD + c4);
        Qs[(c4 + 0) * 64 + row] = t.x;
        Qs[(c4 + 1) * 64 + row] = t.y;
        Qs[(c4 + 2) * 64 + row] = t.z;
        Qs[(c4 + 3) * 64 + row] = t.w;
    }

    float acc[4][4];
    float mi[4], li[4];
    #pragma unroll
    for (int i = 0; i < 4; ++i) {
        mi[i] = -1e30f; li[i] = 0.f;
        #pragma unroll
        for (int j = 0; j < 4; ++j) acc[i][j] = 0.f;
    }

    for (int t0 = 0; t0 < SLEN; t0 += 64) {
        __syncthreads();   // protect Ks/Vs/Ps against previous iteration's readers
        // Load K (transposed) and V (row-major) tiles
        #pragma unroll
        for (int rep = 0; rep < 4; ++rep) {
            int idx = tid + rep * 256;
            int row = idx >> 4;
            int c4  = (idx & 15) << 2;
            float4 tk = *(const float4*)(kb + (size_t)(t0 + row) * NHD + c4);
            Ks[(c4 + 0) * 64 + row] = tk.x;
            Ks[(c4 + 1) * 64 + row] = tk.y;
            Ks[(c4 + 2) * 64 + row] = tk.z;
            Ks[(c4 + 3) * 64 + row] = tk.w;
            float4 tv = *(const float4*)(vb + (size_t)(t0 + row) * NHD + c4);
            *(float4*)&Vs[row * 64 + c4] = tv;
        }
        __syncthreads();

        // S = Q @ K^T  (4x4 per thread)
        float s[4][4];
        #pragma unroll
        for (int i = 0; i < 4; ++i)
            #pragma unroll
            for (int j = 0; j < 4; ++j) s[i][j] = 0.f;

        #pragma unroll 8
        for (int d = 0; d < 64; ++d) {
            float a[4], bb[4];
            *(float4*)a  = *(const float4*)&Qs[d * 64 + ty * 4];
            *(float4*)bb = *(const float4*)&Ks[d * 64 + tx * 4];
            #pragma unroll
            for (int i = 0; i < 4; ++i)
                #pragma unroll
                for (int j = 0; j < 4; ++j)
                    s[i][j] = fmaf(a[i], bb[j], s[i][j]);
        }

        // Online softmax (row reductions across the 16 tx lanes of each half-warp)
        #pragma unroll
        for (int i = 0; i < 4; ++i) {
            float tm = fmaxf(fmaxf(s[i][0], s[i][1]), fmaxf(s[i][2], s[i][3]));
            #pragma unroll
            for (int off = 1; off < 16; off <<= 1)
                tm = fmaxf(tm, __shfl_xor_sync(0xffffffffu, tm, off));
            float mnew = fmaxf(mi[i], tm);
            float corr = __expf(mi[i] - mnew);
            float sum = 0.f;
            #pragma unroll
            for (int j = 0; j < 4; ++j) {
                s[i][j] = __expf(s[i][j] - mnew);
                sum += s[i][j];
            }
            #pragma unroll
            for (int off = 1; off < 16; off <<= 1)
                sum += __shfl_xor_sync(0xffffffffu, sum, off);
            li[i] = li[i] * corr + sum;
            mi[i] = mnew;
            #pragma unroll
            for (int j = 0; j < 4; ++j) acc[i][j] *= corr;
            // stage P in padded smem for the PV GEMM
            #pragma unroll
            for (int j = 0; j < 4; ++j)
                Ps[(ty * 4 + i) * 65 + tx * 4 + j] = s[i][j];
        }
        __syncthreads();

        // acc += P @ V
        #pragma unroll 8
        for (int j = 0; j < 64; ++j) {
            float bb[4];
            *(float4*)bb = *(const float4*)&Vs[j * 64 + tx * 4];
            #pragma unroll
            for (int i = 0; i < 4; ++i) {
                float a = Ps[(ty * 4 + i) * 65 + j];
                #pragma unroll
                for (int c = 0; c < 4; ++c)
                    acc[i][c] = fmaf(a, bb[c], acc[i][c]);
            }
        }
    }

    // epilogue: normalize and store
    #pragma unroll
    for (int i = 0; i < 4; ++i) {
        float inv = 1.f / li[i];
        float4 ov;
        ov.x = acc[i][0] * inv;
        ov.y = acc[i][1] * inv;
        ov.z = acc[i][2] * inv;
        ov.w = acc[i][3] * inv;
        *(float4*)(ob + (size_t)(i0 + ty * 4 + i) * NHD + tx * 4) = ov;
    }
}

// ---------------- launch ----------------
extern "C" void kernel_launch(void* const* d_in, const int* in_sizes, int n_in,
                              void* d_out, int out_size)
{
    const float* Q  = (const float*)d_in[0];
    const float* K  = (const float*)d_in[1];
    const float* V  = (const float*)d_in[2];
    const float* Wq = (const float*)d_in[3];
    const float* bq = (const float*)d_in[4];
    const float* Wk = (const float*)d_in[5];
    const float* bk = (const float*)d_in[6];
    const float* Wv = (const float*)d_in[7];
    const float* bv = (const float*)d_in[8];
    const float* Wo = (const float*)d_in[9];
    const float* bo = (const float*)d_in[10];
    float* out = (float*)d_out;

    float* qp; float* kp; float* vp; float* aop;
    cudaGetSymbolAddress((void**)&qp,  g_q);
    cudaGetSymbolAddress((void**)&kp,  g_k);
    cudaGetSymbolAddress((void**)&vp,  g_v);
    cudaGetSymbolAddress((void**)&aop, g_ao);

    const float scale = 0.125f;  // 1/sqrt(64)

    dim3 gproj(NHD / 128, MROWS / 128);   // (8, 32)
    sgemm_bias<<<gproj, 256>>>(Q, Wq, bq, qp, MROWS, NHD, EMB, scale);
    sgemm_bias<<<gproj, 256>>>(K, Wk, bk, kp, MROWS, NHD, EMB, 1.0f);
    sgemm_bias<<<gproj, 256>>>(V, Wv, bv, vp, MROWS, NHD, EMB, 1.0f);

    static const int kFlashSmem = (3 * 4096 + 64 * 65) * (int)sizeof(float); // 65792 B
    cudaFuncSetAttribute(flash_attn, cudaFuncAttributeMaxDynamicSharedMemorySize, kFlashSmem);
    dim3 gattn(SLEN / 64, NH, BS);        // (32, 16, 2)
    flash_attn<<<gattn, 256, kFlashSmem>>>(qp, kp, vp, aop);

    dim3 gout(EMB / 128, MROWS / 128);    // (8, 32)
    sgemm_bias<<<gout, 256>>>(aop, Wo, bo, out, MROWS, EMB, NHD, 1.0f);
}

// round 3
// speedup vs baseline: 3.3102x; 3.3102x over previous
#include <cuda_runtime.h>
#include <stdint.h>

// Problem constants (fixed by the dataset)
#define BS    2
#define SLEN  2048
#define EMB   1024
#define NHD   1024   // NH*DM
#define NH    16
#define DM    64
#define MROWS (BS * SLEN)   // 4096

// ---------------- scratch (no allocation allowed) ----------------
__device__ float g_q [MROWS * NHD];
__device__ float g_k [MROWS * NHD];
__device__ float g_v [MROWS * NHD];
__device__ float g_ao[MROWS * NHD];

// ---------------- tf32 helpers ----------------
__device__ __forceinline__ uint32_t f2t(float x) {
    uint32_t y;
    asm("cvt.rna.tf32.f32 %0, %1;" : "=r"(y) : "f"(x));
    return y;
}

// D += A(16x8) @ B(8x8), tf32 inputs, fp32 accumulate
// A frag order: a0=(r,c) a1=(r+8,c) a2=(r,c+4) a3=(r+8,c+4)  [PTX ISA]
__device__ __forceinline__ void mma8(float* d, const uint32_t* a, const uint32_t* b) {
    asm volatile(
        "mma.sync.aligned.m16n8k8.row.col.f32.tf32.tf32.f32 "
        "{%0,%1,%2,%3}, {%4,%5,%6,%7}, {%8,%9}, {%0,%1,%2,%3};"
        : "+f"(d[0]), "+f"(d[1]), "+f"(d[2]), "+f"(d[3])
        : "r"(a[0]), "r"(a[1]), "r"(a[2]), "r"(a[3]),
          "r"(b[0]), "r"(b[1]));
}

// ---------------- tf32 GEMM: C = alpha * (A[M,K] @ B[K,N] + bias[N]) ----------------
// BM=128, BN=128, BK=32, 256 threads (8 warps, 2x4), warp tile 64x32.
#define APAD 36   // As[m][k] pitch
#define BPAD 132  // Bs[k][n] pitch

__global__ __launch_bounds__(256) void gemm_tf32(
    const float* __restrict__ A, const float* __restrict__ B,
    const float* __restrict__ bias, float* __restrict__ C,
    int M, int N, int K, float alpha)
{
    __shared__ uint32_t As[128 * APAD];
    __shared__ uint32_t Bs[32 * BPAD];

    const int tid  = threadIdx.x;
    const int lane = tid & 31;
    const int warp = tid >> 5;
    const int bm = blockIdx.y * 128;
    const int bn = blockIdx.x * 128;
    const int wm = (warp >> 2) * 64;   // 0 or 64
    const int wn = (warp & 3) * 32;    // 0,32,64,96

    float acc[4][4][4];
    #pragma unroll
    for (int i = 0; i < 4; ++i)
        #pragma unroll
        for (int j = 0; j < 4; ++j)
            #pragma unroll
            for (int c = 0; c < 4; ++c) acc[i][j][c] = 0.f;

    const int qr = lane >> 2;   // 0..7 (groupID)
    const int qc = lane & 3;    // 0..3 (threadID_in_group)

    for (int k0 = 0; k0 < K; k0 += 32) {
        // A tile: 128 rows x 32 cols -> As[m][k]
        #pragma unroll
        for (int rep = 0; rep < 4; ++rep) {
            int idx = rep * 256 + tid;
            int row = idx >> 3;
            int c4  = (idx & 7) << 2;
            float4 v = *(const float4*)(A + (size_t)(bm + row) * K + k0 + c4);
            uint4 u = make_uint4(f2t(v.x), f2t(v.y), f2t(v.z), f2t(v.w));
            *(uint4*)&As[row * APAD + c4] = u;
        }
        // B tile: 32 rows x 128 cols -> Bs[k][n]
        #pragma unroll
        for (int rep = 0; rep < 4; ++rep) {
            int idx = rep * 256 + tid;
            int kr  = idx >> 5;
            int c4  = (idx & 31) << 2;
            float4 v = *(const float4*)(B + (size_t)(k0 + kr) * N + bn + c4);
            uint4 u = make_uint4(f2t(v.x), f2t(v.y), f2t(v.z), f2t(v.w));
            *(uint4*)&Bs[kr * BPAD + c4] = u;
        }
        __syncthreads();

        #pragma unroll
        for (int kk = 0; kk < 32; kk += 8) {
            uint32_t af[4][4], bf[4][2];
            #pragma unroll
            for (int im = 0; im < 4; ++im) {
                int r = wm + im * 16 + qr;
                int c = kk + qc;
                af[im][0] = As[r * APAD + c];            // (r,   c)
                af[im][1] = As[(r + 8) * APAD + c];      // (r+8, c)
                af[im][2] = As[r * APAD + c + 4];        // (r,   c+4)
                af[im][3] = As[(r + 8) * APAD + c + 4];  // (r+8, c+4)
            }
            #pragma unroll
            for (int in = 0; in < 4; ++in) {
                int c = wn + in * 8 + qr;
                int r = kk + qc;
                bf[in][0] = Bs[r * BPAD + c];
                bf[in][1] = Bs[(r + 4) * BPAD + c];
            }
            #pragma unroll
            for (int im = 0; im < 4; ++im)
                #pragma unroll
                for (int in = 0; in < 4; ++in)
                    mma8(acc[im][in], af[im], bf[in]);
        }
        __syncthreads();
    }

    // epilogue: alpha * (acc + bias)
    #pragma unroll
    for (int im = 0; im < 4; ++im) {
        #pragma unroll
        for (int in = 0; in < 4; ++in) {
            int row = bm + wm + im * 16 + qr;
            int col = bn + wn + in * 8 + qc * 2;
            float b0 = bias[col], b1 = bias[col + 1];
            float2 o0 = make_float2(alpha * (acc[im][in][0] + b0),
                                    alpha * (acc[im][in][1] + b1));
            *(float2*)(C + (size_t)row * N + col) = o0;
            float2 o1 = make_float2(alpha * (acc[im][in][2] + b0),
                                    alpha * (acc[im][in][3] + b1));
            *(float2*)(C + (size_t)(row + 8) * N + col) = o1;
        }
    }
}

// ---------------- Flash attention on tensor cores (tf32) ----------------
// 128 threads (4 warps), 64-row Q block, full D=64, 64-key tiles, online softmax.
#define QPAD 68
#define VPAD 72
#define FLASH_SMEM ((64*QPAD*3 + 64*VPAD) * 4)   // 70656 B

__global__ __launch_bounds__(128) void flash_tc(
    const float* __restrict__ q, const float* __restrict__ k,
    const float* __restrict__ v, float* __restrict__ o)
{
    extern __shared__ uint32_t sm[];
    uint32_t* Qs = sm;                 // [64][QPAD]
    uint32_t* Ks = Qs + 64 * QPAD;     // [64][QPAD]  (stored [s][d])
    uint32_t* Vs = Ks + 64 * QPAD;     // [64][VPAD]  (stored [s][d])
    uint32_t* Ps = Vs + 64 * VPAD;     // [64][QPAD]

    const int tid  = threadIdx.x;
    const int lane = tid & 31;
    const int warp = tid >> 5;
    const int h = blockIdx.y, b = blockIdx.z;
    const int i0 = blockIdx.x * 64;
    const int m0 = warp * 16;
    const int qr = lane >> 2;
    const int qc = lane & 3;

    const size_t base = (size_t)b * SLEN * NHD + (size_t)h * DM;
    const float* qb = q + base;
    const float* kb = k + base;
    const float* vb = v + base;
    float*       ob = o + base;

    // Load Q tile (64x64) as tf32
    #pragma unroll
    for (int rep = 0; rep < 8; ++rep) {
        int idx = rep * 128 + tid;
        int row = idx >> 4;
        int c4  = (idx & 15) << 2;
        float4 t = *(const float4*)(qb + (size_t)(i0 + row) * NHD + c4);
        *(uint4*)&Qs[row * QPAD + c4] = make_uint4(f2t(t.x), f2t(t.y), f2t(t.z), f2t(t.w));
    }

    float ofrag[8][4];
    #pragma unroll
    for (int t = 0; t < 8; ++t)
        #pragma unroll
        for (int c = 0; c < 4; ++c) ofrag[t][c] = 0.f;
    float mrow[2] = {-1e30f, -1e30f};
    float lrow[2] = {0.f, 0.f};

    for (int t0 = 0; t0 < SLEN; t0 += 64) {
        __syncthreads();   // prior iteration's readers of Ks/Vs done
        #pragma unroll
        for (int rep = 0; rep < 8; ++rep) {
            int idx = rep * 128 + tid;
            int row = idx >> 4;
            int c4  = (idx & 15) << 2;
            float4 tk = *(const float4*)(kb + (size_t)(t0 + row) * NHD + c4);
            *(uint4*)&Ks[row * QPAD + c4] = make_uint4(f2t(tk.x), f2t(tk.y), f2t(tk.z), f2t(tk.w));
            float4 tv = *(const float4*)(vb + (size_t)(t0 + row) * NHD + c4);
            *(uint4*)&Vs[row * VPAD + c4] = make_uint4(f2t(tv.x), f2t(tv.y), f2t(tv.z), f2t(tv.w));
        }
        __syncthreads();

        // S = Q @ K^T : per warp rows m0..m0+15, all 64 keys
        float sfrag[8][4];
        #pragma unroll
        for (int t = 0; t < 8; ++t)
            #pragma unroll
            for (int c = 0; c < 4; ++c) sfrag[t][c] = 0.f;

        #pragma unroll
        for (int kd = 0; kd < 64; kd += 8) {
            uint32_t a[4];
            int r = m0 + qr, c = kd + qc;
            a[0] = Qs[r * QPAD + c];            // (r,   c)
            a[1] = Qs[(r + 8) * QPAD + c];      // (r+8, c)
            a[2] = Qs[r * QPAD + c + 4];        // (r,   c+4)
            a[3] = Qs[(r + 8) * QPAD + c + 4];  // (r+8, c+4)
            #pragma unroll
            for (int t = 0; t < 8; ++t) {
                uint32_t bf[2];
                int n = t * 8 + qr;
                bf[0] = Ks[n * QPAD + kd + qc];
                bf[1] = Ks[n * QPAD + kd + 4 + qc];
                mma8(sfrag[t], a, bf);
            }
        }

        // Online softmax: quad (lanes sharing qr) owns rows (m0+qr) and (m0+qr+8)
        #pragma unroll
        for (int hh = 0; hh < 2; ++hh) {
            float mx = -1e30f;
            #pragma unroll
            for (int t = 0; t < 8; ++t)
                mx = fmaxf(mx, fmaxf(sfrag[t][2*hh], sfrag[t][2*hh + 1]));
            mx = fmaxf(mx, __shfl_xor_sync(0xffffffffu, mx, 1));
            mx = fmaxf(mx, __shfl_xor_sync(0xffffffffu, mx, 2));
            float mnew = fmaxf(mrow[hh], mx);
            float corr = __expf(mrow[hh] - mnew);
            float sum = 0.f;
            #pragma unroll
            for (int t = 0; t < 8; ++t) {
                float e0 = __expf(sfrag[t][2*hh]     - mnew);
                float e1 = __expf(sfrag[t][2*hh + 1] - mnew);
                sfrag[t][2*hh] = e0; sfrag[t][2*hh + 1] = e1;
                sum += e0 + e1;
            }
            sum += __shfl_xor_sync(0xffffffffu, sum, 1);
            sum += __shfl_xor_sync(0xffffffffu, sum, 2);
            lrow[hh] = lrow[hh] * corr + sum;
            mrow[hh] = mnew;
            #pragma unroll
            for (int t = 0; t < 8; ++t) {
                ofrag[t][2*hh]     *= corr;
                ofrag[t][2*hh + 1] *= corr;
            }
        }

        // Stage P (tf32) in smem: C-fragment -> A-fragment layout bridge
        {
            int r = m0 + qr;
            #pragma unroll
            for (int t = 0; t < 8; ++t) {
                int c = t * 8 + qc * 2;
                Ps[r * QPAD + c]           = f2t(sfrag[t][0]);
                Ps[r * QPAD + c + 1]       = f2t(sfrag[t][1]);
                Ps[(r + 8) * QPAD + c]     = f2t(sfrag[t][2]);
                Ps[(r + 8) * QPAD + c + 1] = f2t(sfrag[t][3]);
            }
        }
        __syncwarp();   // each warp reads only its own P rows

        // O += P @ V
        #pragma unroll
        for (int ks = 0; ks < 64; ks += 8) {
            uint32_t a[4];
            int r = m0 + qr, c = ks + qc;
            a[0] = Ps[r * QPAD + c];            // (r,   c)
            a[1] = Ps[(r + 8) * QPAD + c];      // (r+8, c)
            a[2] = Ps[r * QPAD + c + 4];        // (r,   c+4)
            a[3] = Ps[(r + 8) * QPAD + c + 4];  // (r+8, c+4)
            #pragma unroll
            for (int t = 0; t < 8; ++t) {
                uint32_t bf[2];
                int n = t * 8 + qr;
                bf[0] = Vs[(ks + qc) * VPAD + n];
                bf[1] = Vs[(ks + 4 + qc) * VPAD + n];
                mma8(ofrag[t], a, bf);
            }
        }
    }

    // Normalize and store O
    float inv0 = 1.f / lrow[0];
    float inv1 = 1.f / lrow[1];
    int r = i0 + m0 + qr;
    #pragma unroll
    for (int t = 0; t < 8; ++t) {
        int col = t * 8 + qc * 2;
        float2 o0 = make_float2(ofrag[t][0] * inv0, ofrag[t][1] * inv0);
        *(float2*)(ob + (size_t)r * NHD + col) = o0;
        float2 o1 = make_float2(ofrag[t][2] * inv1, ofrag[t][3] * inv1);
        *(float2*)(ob + (size_t)(r + 8) * NHD + col) = o1;
    }
}

// ---------------- launch ----------------
extern "C" void kernel_launch(void* const* d_in, const int* in_sizes, int n_in,
                              void* d_out, int out_size)
{
    const float* Q  = (const float*)d_in[0];
    const float* K  = (const float*)d_in[1];
    const float* V  = (const float*)d_in[2];
    const float* Wq = (const float*)d_in[3];
    const float* bq = (const float*)d_in[4];
    const float* Wk = (const float*)d_in[5];
    const float* bk = (const float*)d_in[6];
    const float* Wv = (const float*)d_in[7];
    const float* bv = (const float*)d_in[8];
    const float* Wo = (const float*)d_in[9];
    const float* bo = (const float*)d_in[10];
    float* out = (float*)d_out;

    float* qp; float* kp; float* vp; float* aop;
    cudaGetSymbolAddress((void**)&qp,  g_q);
    cudaGetSymbolAddress((void**)&kp,  g_k);
    cudaGetSymbolAddress((void**)&vp,  g_v);
    cudaGetSymbolAddress((void**)&aop, g_ao);

    const float scale = 0.125f;  // 1/sqrt(64), folded into Q projection

    dim3 gproj(NHD / 128, MROWS / 128);   // (8, 32)
    gemm_tf32<<<gproj, 256>>>(Q, Wq, bq, qp, MROWS, NHD, EMB, scale);
    gemm_tf32<<<gproj, 256>>>(K, Wk, bk, kp, MROWS, NHD, EMB, 1.0f);
    gemm_tf32<<<gproj, 256>>>(V, Wv, bv, vp, MROWS, NHD, EMB, 1.0f);

    cudaFuncSetAttribute(flash_tc, cudaFuncAttributeMaxDynamicSharedMemorySize, FLASH_SMEM);
    dim3 gattn(SLEN / 64, NH, BS);        // (32, 16, 2)
    flash_tc<<<gattn, 128, FLASH_SMEM>>>(qp, kp, vp, aop);

    dim3 gout(EMB / 128, MROWS / 128);    // (8, 32)
    gemm_tf32<<<gout, 256>>>(aop, Wo, bo, out, MROWS, EMB, NHD, 1.0f);
}

// round 4
// speedup vs baseline: 3.3935x; 1.0251x over previous
#include <cuda_runtime.h>
#include <stdint.h>

// Problem constants (fixed by the dataset)
#define BS    2
#define SLEN  2048
#define EMB   1024
#define NHD   1024   // NH*DM
#define NH    16
#define DM    64
#define MROWS (BS * SLEN)   // 4096

// ---------------- scratch (no allocation allowed) ----------------
__device__ float g_q [MROWS * NHD];
__device__ float g_k [MROWS * NHD];
__device__ float g_v [MROWS * NHD];
__device__ float g_ao[MROWS * NHD];

// ---------------- helpers ----------------
__device__ __forceinline__ uint32_t f2t(float x) {
    uint32_t y;
    asm("cvt.rna.tf32.f32 %0, %1;" : "=r"(y) : "f"(x));
    return y;
}
__device__ __forceinline__ float fexp2(float x) {
    float y;
    asm("ex2.approx.ftz.f32 %0, %1;" : "=f"(y) : "f"(x));
    return y;
}
// D += A(16x8) @ B(8x8), tf32 inputs, fp32 accumulate
// A frag order: a0=(r,c) a1=(r+8,c) a2=(r,c+4) a3=(r+8,c+4)
__device__ __forceinline__ void mma8(float* d, const uint32_t* a, const uint32_t* b) {
    asm volatile(
        "mma.sync.aligned.m16n8k8.row.col.f32.tf32.tf32.f32 "
        "{%0,%1,%2,%3}, {%4,%5,%6,%7}, {%8,%9}, {%0,%1,%2,%3};"
        : "+f"(d[0]), "+f"(d[1]), "+f"(d[2]), "+f"(d[3])
        : "r"(a[0]), "r"(a[1]), "r"(a[2]), "r"(a[3]),
          "r"(b[0]), "r"(b[1]));
}
__device__ __forceinline__ void cp16(uint32_t saddr, const void* gptr) {
    asm volatile("cp.async.ca.shared.global [%0], [%1], 16;\n"
                 :: "r"(saddr), "l"(gptr));
}
__device__ __forceinline__ uint32_t s2u(const void* p) {
    return (uint32_t)__cvta_generic_to_shared(p);
}

// ---------------- tf32 GEMM: C = alpha * (A[M,K] @ B[K,N] + bias[N]) ----------------
// BM=128, BN=128, BK=32, 256 threads (8 warps, 2x4), warp tile 64x32.
// 3-stage cp.async pipeline, fp32 in smem, tf32 cvt at fragment load.
#define APAD 36
#define BPAD 132
#define GSTG 3
#define GEMM_SMEM ((GSTG * (128 * APAD + 32 * BPAD)) * 4)   // 105984 B

__global__ __launch_bounds__(256) void gemm_tf32(
    const float* __restrict__ A, const float* __restrict__ B,
    const float* __restrict__ bias, float* __restrict__ C,
    int M, int N, int K, float alpha)
{
    extern __shared__ float gsm[];
    float* Asf = gsm;                        // [GSTG][128*APAD]
    float* Bsf = gsm + GSTG * 128 * APAD;    // [GSTG][32*BPAD]

    const int tid  = threadIdx.x;
    const int lane = tid & 31;
    const int warp = tid >> 5;
    const int bm = blockIdx.y * 128;
    const int bn = blockIdx.x * 128;
    const int wm = (warp >> 2) * 64;
    const int wn = (warp & 3) * 32;
    const int qr = lane >> 2;
    const int qc = lane & 3;

    // loader indices
    const int arow = tid >> 1;           // unused path removed; cp.async indices:
    (void)arow;

    float acc[4][4][4];
    #pragma unroll
    for (int i = 0; i < 4; ++i)
        #pragma unroll
        for (int j = 0; j < 4; ++j)
            #pragma unroll
            for (int c = 0; c < 4; ++c) acc[i][j][c] = 0.f;

    const int nt = K / 32;

    // ---- issue one 128x32 A tile + 32x128 B tile into stage s ----
    auto issue = [&](int s, int k0) {
        float* as = Asf + s * 128 * APAD;
        float* bs = Bsf + s * 32 * BPAD;
        #pragma unroll
        for (int rep = 0; rep < 4; ++rep) {
            int idx = rep * 256 + tid;
            int row = idx >> 3;            // 0..127
            int c4  = (idx & 7) << 2;      // 0..28
            cp16(s2u(as + row * APAD + c4),
                 A + (size_t)(bm + row) * K + k0 + c4);
        }
        #pragma unroll
        for (int rep = 0; rep < 4; ++rep) {
            int idx = rep * 256 + tid;
            int kr  = idx >> 5;            // 0..31
            int c4  = (idx & 31) << 2;     // 0..124
            cp16(s2u(bs + kr * BPAD + c4),
                 B + (size_t)(k0 + kr) * N + bn + c4);
        }
        asm volatile("cp.async.commit_group;\n");
    };

    issue(0, 0);
    issue(1, 32);

    for (int it = 0; it < nt; ++it) {
        if (it + 1 < nt) { asm volatile("cp.async.wait_group 1;\n"); }
        else             { asm volatile("cp.async.wait_group 0;\n"); }
        __syncthreads();
        if (it + 2 < nt) issue((it + 2) % GSTG, (it + 2) * 32);

        const float* as = Asf + (it % GSTG) * 128 * APAD;
        const float* bs = Bsf + (it % GSTG) * 32 * BPAD;

        #pragma unroll
        for (int kk = 0; kk < 32; kk += 8) {
            uint32_t af[4][4], bf[4][2];
            #pragma unroll
            for (int im = 0; im < 4; ++im) {
                int r = wm + im * 16 + qr;
                int c = kk + qc;
                af[im][0] = f2t(as[r * APAD + c]);
                af[im][1] = f2t(as[(r + 8) * APAD + c]);
                af[im][2] = f2t(as[r * APAD + c + 4]);
                af[im][3] = f2t(as[(r + 8) * APAD + c + 4]);
            }
            #pragma unroll
            for (int in = 0; in < 4; ++in) {
                int c = wn + in * 8 + qr;
                int r = kk + qc;
                bf[in][0] = f2t(bs[r * BPAD + c]);
                bf[in][1] = f2t(bs[(r + 4) * BPAD + c]);
            }
            #pragma unroll
            for (int im = 0; im < 4; ++im)
                #pragma unroll
                for (int in = 0; in < 4; ++in)
                    mma8(acc[im][in], af[im], bf[in]);
        }
    }

    // epilogue: alpha * (acc + bias)
    #pragma unroll
    for (int im = 0; im < 4; ++im) {
        #pragma unroll
        for (int in = 0; in < 4; ++in) {
            int row = bm + wm + im * 16 + qr;
            int col = bn + wn + in * 8 + qc * 2;
            float b0 = bias[col], b1 = bias[col + 1];
            float2 o0 = make_float2(alpha * (acc[im][in][0] + b0),
                                    alpha * (acc[im][in][1] + b1));
            *(float2*)(C + (size_t)row * N + col) = o0;
            float2 o1 = make_float2(alpha * (acc[im][in][2] + b0),
                                    alpha * (acc[im][in][3] + b1));
            *(float2*)(C + (size_t)(row + 8) * N + col) = o1;
        }
    }
}

// ---------------- Flash attention on tensor cores (tf32) ----------------
// 128 threads (4 warps), 128-row Q block (32 rows/warp), 64-key tiles.
// Q projection pre-scaled by (1/sqrt(DM))*log2(e); softmax uses exp2.
#define QPAD 68
#define PPAD 68
#define VPAD 72
#define FLASH_SMEM ((128*QPAD + 128*PPAD + 64*QPAD + 64*VPAD) * 4)   // 105472 B

__global__ __launch_bounds__(128) void flash_tc(
    const float* __restrict__ q, const float* __restrict__ k,
    const float* __restrict__ v, float* __restrict__ o)
{
    extern __shared__ uint32_t sm[];
    uint32_t* Qs = sm;                    // [128][QPAD]
    uint32_t* Ps = Qs + 128 * QPAD;       // [128][PPAD]
    uint32_t* Ks = Ps + 128 * PPAD;       // [64][QPAD]  ([s][d])
    uint32_t* Vs = Ks + 64 * QPAD;        // [64][VPAD]  ([s][d])

    const int tid  = threadIdx.x;
    const int lane = tid & 31;
    const int warp = tid >> 5;
    const int h = blockIdx.y, b = blockIdx.z;
    const int i0 = blockIdx.x * 128;
    const int m0 = warp * 32;
    const int qr = lane >> 2;
    const int qc = lane & 3;

    const size_t base = (size_t)b * SLEN * NHD + (size_t)h * DM;
    const float* qb = q + base;
    const float* kb = k + base;
    const float* vb = v + base;
    float*       ob = o + base;

    // Load Q tile (128x64) as tf32
    #pragma unroll
    for (int rep = 0; rep < 16; ++rep) {
        int idx = rep * 128 + tid;
        int row = idx >> 4;
        int c4  = (idx & 15) << 2;
        float4 t = *(const float4*)(qb + (size_t)(i0 + row) * NHD + c4);
        *(uint4*)&Qs[row * QPAD + c4] = make_uint4(f2t(t.x), f2t(t.y), f2t(t.z), f2t(t.w));
    }

    float ofrag[2][8][4];
    #pragma unroll
    for (int im = 0; im < 2; ++im)
        #pragma unroll
        for (int t = 0; t < 8; ++t)
            #pragma unroll
            for (int c = 0; c < 4; ++c) ofrag[im][t][c] = 0.f;
    float mrow[4] = {-1e30f, -1e30f, -1e30f, -1e30f};
    float lrow[4] = {0.f, 0.f, 0.f, 0.f};

    for (int t0 = 0; t0 < SLEN; t0 += 64) {
        __syncthreads();   // prior readers of Ks/Vs done
        #pragma unroll
        for (int rep = 0; rep < 8; ++rep) {
            int idx = rep * 128 + tid;
            int row = idx >> 4;
            int c4  = (idx & 15) << 2;
            float4 tk = *(const float4*)(kb + (size_t)(t0 + row) * NHD + c4);
            *(uint4*)&Ks[row * QPAD + c4] = make_uint4(f2t(tk.x), f2t(tk.y), f2t(tk.z), f2t(tk.w));
            float4 tv = *(const float4*)(vb + (size_t)(t0 + row) * NHD + c4);
            *(uint4*)&Vs[row * VPAD + c4] = make_uint4(f2t(tv.x), f2t(tv.y), f2t(tv.z), f2t(tv.w));
        }
        __syncthreads();

        // S = Q @ K^T : per warp rows m0..m0+31, all 64 keys
        float sfrag[2][8][4];
        #pragma unroll
        for (int im = 0; im < 2; ++im)
            #pragma unroll
            for (int t = 0; t < 8; ++t)
                #pragma unroll
                for (int c = 0; c < 4; ++c) sfrag[im][t][c] = 0.f;

        #pragma unroll
        for (int kd = 0; kd < 64; kd += 8) {
            uint32_t a[2][4];
            #pragma unroll
            for (int im = 0; im < 2; ++im) {
                int r = m0 + im * 16 + qr, c = kd + qc;
                a[im][0] = Qs[r * QPAD + c];
                a[im][1] = Qs[(r + 8) * QPAD + c];
                a[im][2] = Qs[r * QPAD + c + 4];
                a[im][3] = Qs[(r + 8) * QPAD + c + 4];
            }
            #pragma unroll
            for (int t = 0; t < 8; ++t) {
                uint32_t bf[2];
                int n = t * 8 + qr;
                bf[0] = Ks[n * QPAD + kd + qc];
                bf[1] = Ks[n * QPAD + kd + 4 + qc];
                mma8(sfrag[0][t], a[0], bf);
                mma8(sfrag[1][t], a[1], bf);
            }
        }

        // Online softmax (exp2 domain): state s = im*2 + hh
        #pragma unroll
        for (int im = 0; im < 2; ++im) {
            #pragma unroll
            for (int hh = 0; hh < 2; ++hh) {
                const int s = im * 2 + hh;
                float mx = -1e30f;
                #pragma unroll
                for (int t = 0; t < 8; ++t)
                    mx = fmaxf(mx, fmaxf(sfrag[im][t][2*hh], sfrag[im][t][2*hh + 1]));
                mx = fmaxf(mx, __shfl_xor_sync(0xffffffffu, mx, 1));
                mx = fmaxf(mx, __shfl_xor_sync(0xffffffffu, mx, 2));
                float mnew = fmaxf(mrow[s], mx);
                float corr = fexp2(mrow[s] - mnew);
                float sum = 0.f;
                #pragma unroll
                for (int t = 0; t < 8; ++t) {
                    float e0 = fexp2(sfrag[im][t][2*hh]     - mnew);
                    float e1 = fexp2(sfrag[im][t][2*hh + 1] - mnew);
                    sfrag[im][t][2*hh] = e0; sfrag[im][t][2*hh + 1] = e1;
                    sum += e0 + e1;
                }
                sum += __shfl_xor_sync(0xffffffffu, sum, 1);
                sum += __shfl_xor_sync(0xffffffffu, sum, 2);
                lrow[s] = lrow[s] * corr + sum;
                mrow[s] = mnew;
                #pragma unroll
                for (int t = 0; t < 8; ++t) {
                    ofrag[im][t][2*hh]     *= corr;
                    ofrag[im][t][2*hh + 1] *= corr;
                }
            }
        }

        // Stage P (tf32) in smem: C-fragment -> A-fragment bridge (uint2 stores)
        #pragma unroll
        for (int im = 0; im < 2; ++im) {
            int r = m0 + im * 16 + qr;
            #pragma unroll
            for (int t = 0; t < 8; ++t) {
                int c = t * 8 + qc * 2;
                uint2 u0 = make_uint2(f2t(sfrag[im][t][0]), f2t(sfrag[im][t][1]));
                *(uint2*)&Ps[r * PPAD + c] = u0;
                uint2 u1 = make_uint2(f2t(sfrag[im][t][2]), f2t(sfrag[im][t][3]));
                *(uint2*)&Ps[(r + 8) * PPAD + c] = u1;
            }
        }
        __syncwarp();   // each warp reads only its own P rows

        // O += P @ V
        #pragma unroll
        for (int ks = 0; ks < 64; ks += 8) {
            uint32_t a[2][4];
            #pragma unroll
            for (int im = 0; im < 2; ++im) {
                int r = m0 + im * 16 + qr, c = ks + qc;
                a[im][0] = Ps[r * PPAD + c];
                a[im][1] = Ps[(r + 8) * PPAD + c];
                a[im][2] = Ps[r * PPAD + c + 4];
                a[im][3] = Ps[(r + 8) * PPAD + c + 4];
            }
            #pragma unroll
            for (int t = 0; t < 8; ++t) {
                uint32_t bf[2];
                int n = t * 8 + qr;
                bf[0] = Vs[(ks + qc) * VPAD + n];
                bf[1] = Vs[(ks + 4 + qc) * VPAD + n];
                mma8(ofrag[0][t], a[0], bf);
                mma8(ofrag[1][t], a[1], bf);
            }
        }
    }

    // Normalize and store O
    #pragma unroll
    for (int im = 0; im < 2; ++im) {
        float inv0 = 1.f / lrow[im * 2];
        float inv1 = 1.f / lrow[im * 2 + 1];
        int r = i0 + m0 + im * 16 + qr;
        #pragma unroll
        for (int t = 0; t < 8; ++t) {
            int col = t * 8 + qc * 2;
            float2 o0 = make_float2(ofrag[im][t][0] * inv0, ofrag[im][t][1] * inv0);
            *(float2*)(ob + (size_t)r * NHD + col) = o0;
            float2 o1 = make_float2(ofrag[im][t][2] * inv1, ofrag[im][t][3] * inv1);
            *(float2*)(ob + (size_t)(r + 8) * NHD + col) = o1;
        }
    }
}

// ---------------- launch ----------------
extern "C" void kernel_launch(void* const* d_in, const int* in_sizes, int n_in,
                              void* d_out, int out_size)
{
    const float* Q  = (const float*)d_in[0];
    const float* K  = (const float*)d_in[1];
    const float* V  = (const float*)d_in[2];
    const float* Wq = (const float*)d_in[3];
    const float* bq = (const float*)d_in[4];
    const float* Wk = (const float*)d_in[5];
    const float* bk = (const float*)d_in[6];
    const float* Wv = (const float*)d_in[7];
    const float* bv = (const float*)d_in[8];
    const float* Wo = (const float*)d_in[9];
    const float* bo = (const float*)d_in[10];
    float* out = (float*)d_out;

    float* qp; float* kp; float* vp; float* aop;
    cudaGetSymbolAddress((void**)&qp,  g_q);
    cudaGetSymbolAddress((void**)&kp,  g_k);
    cudaGetSymbolAddress((void**)&vp,  g_v);
    cudaGetSymbolAddress((void**)&aop, g_ao);

    // 1/sqrt(64) * log2(e): softmax computed in exp2 domain
    const float scale = 0.125f * 1.4426950408889634f;

    cudaFuncSetAttribute(gemm_tf32, cudaFuncAttributeMaxDynamicSharedMemorySize, GEMM_SMEM);
    cudaFuncSetAttribute(flash_tc,  cudaFuncAttributeMaxDynamicSharedMemorySize, FLASH_SMEM);

    dim3 gproj(NHD / 128, MROWS / 128);   // (8, 32)
    gemm_tf32<<<gproj, 256, GEMM_SMEM>>>(Q, Wq, bq, qp, MROWS, NHD, EMB, scale);
    gemm_tf32<<<gproj, 256, GEMM_SMEM>>>(K, Wk, bk, kp, MROWS, NHD, EMB, 1.0f);
    gemm_tf32<<<gproj, 256, GEMM_SMEM>>>(V, Wv, bv, vp, MROWS, NHD, EMB, 1.0f);

    dim3 gattn(SLEN / 128, NH, BS);       // (16, 16, 2)
    flash_tc<<<gattn, 128, FLASH_SMEM>>>(qp, kp, vp, aop);

    dim3 gout(EMB / 128, MROWS / 128);    // (8, 32)
    gemm_tf32<<<gout, 256, GEMM_SMEM>>>(aop, Wo, bo, out, MROWS, EMB, NHD, 1.0f);
}

// round 5
// speedup vs baseline: 5.4919x; 1.6184x over previous
#include <cuda_runtime.h>
#include <cuda_fp16.h>
#include <stdint.h>

// Problem constants (fixed by the dataset)
#define BS    2
#define SLEN  2048
#define EMB   1024
#define NHD   1024   // NH*DM
#define NH    16
#define DM    64
#define MROWS (BS * SLEN)   // 4096

// ---------------- scratch (no allocation allowed) ----------------
__device__ float g_q [MROWS * NHD];
__device__ float g_k [MROWS * NHD];
__device__ float g_v [MROWS * NHD];
__device__ float g_ao[MROWS * NHD];

// ---------------- helpers ----------------
// pack two fp32 -> half2 {lo, hi} (first asm source -> upper half)
__device__ __forceinline__ uint32_t h2(float lo, float hi) {
    uint32_t r;
    asm("cvt.rn.f16x2.f32 %0, %1, %2;" : "=r"(r) : "f"(hi), "f"(lo));
    return r;
}
__device__ __forceinline__ float fexp2(float x) {
    float y;
    asm("ex2.approx.ftz.f32 %0, %1;" : "=f"(y) : "f"(x));
    return y;
}
// D += A(16x16) @ B(16x8), fp16 inputs, fp32 accumulate
// A frags: a0=(r,2c,2c+1) a1=(r+8,..) a2=(r,2c+8,2c+9) a3=(r+8,+8)
// B frags: b0=(2c..2c+1, n) b1=(2c+8..2c+9, n)
__device__ __forceinline__ void mma16(float* d, const uint32_t* a, const uint32_t* b) {
    asm volatile(
        "mma.sync.aligned.m16n8k16.row.col.f32.f16.f16.f32 "
        "{%0,%1,%2,%3}, {%4,%5,%6,%7}, {%8,%9}, {%0,%1,%2,%3};"
        : "+f"(d[0]), "+f"(d[1]), "+f"(d[2]), "+f"(d[3])
        : "r"(a[0]), "r"(a[1]), "r"(a[2]), "r"(a[3]),
          "r"(b[0]), "r"(b[1]));
}

// ---------------- fp16 GEMM: C = alpha * (A[M,K] @ B[K,N] + bias[N]) ----------------
// BM=128, BN=128, BK=32, 256 threads (8 warps 2x4), warp tile 64x32.
// 2-stage smem, register double-buffered global loads, 1 sync per k-tile.
#define AP 20    // Asp pitch in half2 words (row = 16 half2 + pad) -> conflict-free frags
#define BP 132   // Bsp pitch in half2 words
#define ASZ (128 * AP)
#define BSZ (16 * BP)

__global__ __launch_bounds__(256) void gemm_h(
    const float* __restrict__ A, const float* __restrict__ B,
    const float* __restrict__ bias, float* __restrict__ C,
    int M, int N, int K, float alpha)
{
    __shared__ uint32_t As[2 * ASZ];   // [m][kpair] half2
    __shared__ uint32_t Bs[2 * BSZ];   // [kpair][n] half2 {B[2k][n], B[2k+1][n]}

    const int tid  = threadIdx.x;
    const int lane = tid & 31;
    const int warp = tid >> 5;
    const int bm = blockIdx.y * 128;
    const int bn = blockIdx.x * 128;
    const int wm = (warp >> 2) * 64;
    const int wn = (warp & 3) * 32;
    const int qr = lane >> 2;
    const int qc = lane & 3;

    const int ar  = tid >> 3;          // A row (+rep*32)
    const int ac  = (tid & 7) << 2;    // A col4
    const int bpr = tid >> 5;          // B pair-row (+rep*8)
    const int bn4 = (tid & 31) << 2;   // B col4

    float4 la[4], lb0[2], lb1[2];

    float acc[4][4][4];
    #pragma unroll
    for (int i = 0; i < 4; ++i)
        #pragma unroll
        for (int j = 0; j < 4; ++j)
            #pragma unroll
            for (int c = 0; c < 4; ++c) acc[i][j][c] = 0.f;

    auto ldg = [&](int k0) {
        #pragma unroll
        for (int r = 0; r < 4; ++r)
            la[r] = *(const float4*)(A + (size_t)(bm + ar + r * 32) * K + k0 + ac);
        #pragma unroll
        for (int r = 0; r < 2; ++r) {
            int pr = bpr + r * 8;
            lb0[r] = *(const float4*)(B + (size_t)(k0 + 2 * pr)     * N + bn + bn4);
            lb1[r] = *(const float4*)(B + (size_t)(k0 + 2 * pr + 1) * N + bn + bn4);
        }
    };
    auto sts = [&](int s) {
        uint32_t* as = As + s * ASZ;
        uint32_t* bs = Bs + s * BSZ;
        #pragma unroll
        for (int r = 0; r < 4; ++r) {
            uint2 u = make_uint2(h2(la[r].x, la[r].y), h2(la[r].z, la[r].w));
            *(uint2*)&as[(ar + r * 32) * AP + (ac >> 1)] = u;
        }
        #pragma unroll
        for (int r = 0; r < 2; ++r) {
            int pr = bpr + r * 8;
            uint4 u = make_uint4(h2(lb0[r].x, lb1[r].x), h2(lb0[r].y, lb1[r].y),
                                 h2(lb0[r].z, lb1[r].z), h2(lb0[r].w, lb1[r].w));
            *(uint4*)&bs[pr * BP + bn4] = u;
        }
    };

    const int nt = K >> 5;
    ldg(0); sts(0); __syncthreads();

    for (int it = 0; it < nt; ++it) {
        if (it + 1 < nt) ldg((it + 1) * 32);

        const uint32_t* as = As + (it & 1) * ASZ;
        const uint32_t* bs = Bs + (it & 1) * BSZ;

        #pragma unroll
        for (int kb = 0; kb < 2; ++kb) {     // two k16 chunks per BK=32
            uint32_t af[4][4], bf[4][2];
            #pragma unroll
            for (int im = 0; im < 4; ++im) {
                int base = (wm + im * 16 + qr) * AP + kb * 8 + qc;
                af[im][0] = as[base];
                af[im][1] = as[base + 8 * AP];
                af[im][2] = as[base + 4];
                af[im][3] = as[base + 8 * AP + 4];
            }
            #pragma unroll
            for (int in = 0; in < 4; ++in) {
                int n = wn + in * 8 + qr;
                bf[in][0] = bs[(kb * 8 + qc) * BP + n];
                bf[in][1] = bs[(kb * 8 + 4 + qc) * BP + n];
            }
            #pragma unroll
            for (int im = 0; im < 4; ++im)
                #pragma unroll
                for (int in = 0; in < 4; ++in)
                    mma16(acc[im][in], af[im], bf[in]);
        }

        if (it + 1 < nt) { sts((it + 1) & 1); __syncthreads(); }
    }

    // epilogue: alpha * (acc + bias)
    #pragma unroll
    for (int im = 0; im < 4; ++im) {
        #pragma unroll
        for (int in = 0; in < 4; ++in) {
            int row = bm + wm + im * 16 + qr;
            int col = bn + wn + in * 8 + qc * 2;
            float b0 = bias[col], b1 = bias[col + 1];
            float2 o0 = make_float2(alpha * (acc[im][in][0] + b0),
                                    alpha * (acc[im][in][1] + b1));
            *(float2*)(C + (size_t)row * N + col) = o0;
            float2 o1 = make_float2(alpha * (acc[im][in][2] + b0),
                                    alpha * (acc[im][in][3] + b1));
            *(float2*)(C + (size_t)(row + 8) * N + col) = o1;
        }
    }
}

// ---------------- Flash attention, fp16 tensor cores, FA2 P-register reuse ----------------
// 128 threads (4 warps x 32 Q rows = 128-row block), 64-key tiles.
// Q pre-scaled by (1/sqrt(DM))*log2(e); softmax in exp2 domain.
#define QP 36   // pitch in half2 words (72 halves/row)

__global__ __launch_bounds__(128) void flash_h(
    const float* __restrict__ q, const float* __restrict__ k,
    const float* __restrict__ v, float* __restrict__ o)
{
    __shared__ uint32_t Qs[128 * QP];  // [row][d] half2, 18KB
    __shared__ uint32_t Ks[64 * QP];   // [key][d] half2, 9KB
    __shared__ uint32_t Vs[64 * QP];   // [key][d] half2, 9KB
    const __half* Vh = (const __half*)Vs;

    const int tid  = threadIdx.x;
    const int lane = tid & 31;
    const int warp = tid >> 5;
    const int h = blockIdx.y, b = blockIdx.z;
    const int i0 = blockIdx.x * 128;
    const int m0 = warp * 32;
    const int qr = lane >> 2;
    const int qc = lane & 3;

    const size_t base = (size_t)b * SLEN * NHD + (size_t)h * DM;
    const float* qb = q + base;
    const float* kb = k + base;
    const float* vb = v + base;
    float*       ob = o + base;

    // Load Q tile (128x64) -> fp16 smem
    #pragma unroll
    for (int rep = 0; rep < 16; ++rep) {
        int idx = rep * 128 + tid;
        int row = idx >> 4;
        int c4  = (idx & 15) << 2;
        float4 t = *(const float4*)(qb + (size_t)(i0 + row) * NHD + c4);
        *(uint2*)&Qs[row * QP + (c4 >> 1)] = make_uint2(h2(t.x, t.y), h2(t.z, t.w));
    }

    float ofrag[2][8][4];
    #pragma unroll
    for (int im = 0; im < 2; ++im)
        #pragma unroll
        for (int t = 0; t < 8; ++t)
            #pragma unroll
            for (int c = 0; c < 4; ++c) ofrag[im][t][c] = 0.f;
    float mrow[4] = {-1e30f, -1e30f, -1e30f, -1e30f};
    float lrow[4] = {0.f, 0.f, 0.f, 0.f};

    for (int t0 = 0; t0 < SLEN; t0 += 64) {
        __syncthreads();   // prior readers of Ks/Vs done
        #pragma unroll
        for (int rep = 0; rep < 8; ++rep) {
            int idx = rep * 128 + tid;
            int row = idx >> 4;
            int c4  = (idx & 15) << 2;
            float4 tk = *(const float4*)(kb + (size_t)(t0 + row) * NHD + c4);
            *(uint2*)&Ks[row * QP + (c4 >> 1)] = make_uint2(h2(tk.x, tk.y), h2(tk.z, tk.w));
            float4 tv = *(const float4*)(vb + (size_t)(t0 + row) * NHD + c4);
            *(uint2*)&Vs[row * QP + (c4 >> 1)] = make_uint2(h2(tv.x, tv.y), h2(tv.z, tv.w));
        }
        __syncthreads();

        // S = Q @ K^T : per warp rows m0..m0+31, 64 keys
        float sfrag[2][8][4];
        #pragma unroll
        for (int im = 0; im < 2; ++im)
            #pragma unroll
            for (int t = 0; t < 8; ++t)
                #pragma unroll
                for (int c = 0; c < 4; ++c) sfrag[im][t][c] = 0.f;

        #pragma unroll
        for (int kd = 0; kd < 4; ++kd) {     // 4 k16 chunks over D=64
            uint32_t a[2][4];
            #pragma unroll
            for (int im = 0; im < 2; ++im) {
                int bse = (m0 + im * 16 + qr) * QP + kd * 8 + qc;
                a[im][0] = Qs[bse];
                a[im][1] = Qs[bse + 8 * QP];
                a[im][2] = Qs[bse + 4];
                a[im][3] = Qs[bse + 8 * QP + 4];
            }
            #pragma unroll
            for (int t = 0; t < 8; ++t) {
                int n = t * 8 + qr;
                uint32_t bf[2];
                bf[0] = Ks[n * QP + kd * 8 + qc];
                bf[1] = Ks[n * QP + kd * 8 + 4 + qc];
                mma16(sfrag[0][t], a[0], bf);
                mma16(sfrag[1][t], a[1], bf);
            }
        }

        // Online softmax (exp2 domain)
        #pragma unroll
        for (int im = 0; im < 2; ++im) {
            #pragma unroll
            for (int hh = 0; hh < 2; ++hh) {
                const int s = im * 2 + hh;
                float mx = -1e30f;
                #pragma unroll
                for (int t = 0; t < 8; ++t)
                    mx = fmaxf(mx, fmaxf(sfrag[im][t][2*hh], sfrag[im][t][2*hh + 1]));
                mx = fmaxf(mx, __shfl_xor_sync(0xffffffffu, mx, 1));
                mx = fmaxf(mx, __shfl_xor_sync(0xffffffffu, mx, 2));
                float mnew = fmaxf(mrow[s], mx);
                float corr = fexp2(mrow[s] - mnew);
                float sum = 0.f;
                #pragma unroll
                for (int t = 0; t < 8; ++t) {
                    float e0 = fexp2(sfrag[im][t][2*hh]     - mnew);
                    float e1 = fexp2(sfrag[im][t][2*hh + 1] - mnew);
                    sfrag[im][t][2*hh] = e0; sfrag[im][t][2*hh + 1] = e1;
                    sum += e0 + e1;
                }
                sum += __shfl_xor_sync(0xffffffffu, sum, 1);
                sum += __shfl_xor_sync(0xffffffffu, sum, 2);
                lrow[s] = lrow[s] * corr + sum;
                mrow[s] = mnew;
                #pragma unroll
                for (int t = 0; t < 8; ++t) {
                    ofrag[im][t][2*hh]     *= corr;
                    ofrag[im][t][2*hh + 1] *= corr;
                }
            }
        }

        // P: C-fragment -> A-fragment entirely in registers (fp16 pack)
        uint32_t p01[2][8], p23[2][8];
        #pragma unroll
        for (int im = 0; im < 2; ++im)
            #pragma unroll
            for (int t = 0; t < 8; ++t) {
                p01[im][t] = h2(sfrag[im][t][0], sfrag[im][t][1]);
                p23[im][t] = h2(sfrag[im][t][2], sfrag[im][t][3]);
            }

        // O += P @ V  (A from registers, B from Vs via u16 pair loads)
        #pragma unroll
        for (int g = 0; g < 4; ++g) {        // key chunks of 16
            uint32_t a0[4] = { p01[0][2*g], p23[0][2*g], p01[0][2*g+1], p23[0][2*g+1] };
            uint32_t a1[4] = { p01[1][2*g], p23[1][2*g], p01[1][2*g+1], p23[1][2*g+1] };
            #pragma unroll
            for (int t = 0; t < 8; ++t) {
                int n = t * 8 + qr;
                int k0 = 16 * g + 2 * qc;
                uint32_t bf[2];
                {
                    uint32_t lo = *(const unsigned short*)(Vh + (size_t)k0 * 72 + n);
                    uint32_t hi = *(const unsigned short*)(Vh + (size_t)(k0 + 1) * 72 + n);
                    bf[0] = lo | (hi << 16);
                }
                {
                    uint32_t lo = *(const unsigned short*)(Vh + (size_t)(k0 + 8) * 72 + n);
                    uint32_t hi = *(const unsigned short*)(Vh + (size_t)(k0 + 9) * 72 + n);
                    bf[1] = lo | (hi << 16);
                }
                mma16(ofrag[0][t], a0, bf);
                mma16(ofrag[1][t], a1, bf);
            }
        }
    }

    // Normalize and store O
    #pragma unroll
    for (int im = 0; im < 2; ++im) {
        float inv0 = 1.f / lrow[im * 2];
        float inv1 = 1.f / lrow[im * 2 + 1];
        int r = i0 + m0 + im * 16 + qr;
        #pragma unroll
        for (int t = 0; t < 8; ++t) {
            int col = t * 8 + qc * 2;
            float2 o0 = make_float2(ofrag[im][t][0] * inv0, ofrag[im][t][1] * inv0);
            *(float2*)(ob + (size_t)r * NHD + col) = o0;
            float2 o1 = make_float2(ofrag[im][t][2] * inv1, ofrag[im][t][3] * inv1);
            *(float2*)(ob + (size_t)(r + 8) * NHD + col) = o1;
        }
    }
}

// ---------------- launch ----------------
extern "C" void kernel_launch(void* const* d_in, const int* in_sizes, int n_in,
                              void* d_out, int out_size)
{
    const float* Q  = (const float*)d_in[0];
    const float* K  = (const float*)d_in[1];
    const float* V  = (const float*)d_in[2];
    const float* Wq = (const float*)d_in[3];
    const float* bq = (const float*)d_in[4];
    const float* Wk = (const float*)d_in[5];
    const float* bk = (const float*)d_in[6];
    const float* Wv = (const float*)d_in[7];
    const float* bv = (const float*)d_in[8];
    const float* Wo = (const float*)d_in[9];
    const float* bo = (const float*)d_in[10];
    float* out = (float*)d_out;

    float* qp; float* kp; float* vp; float* aop;
    cudaGetSymbolAddress((void**)&qp,  g_q);
    cudaGetSymbolAddress((void**)&kp,  g_k);
    cudaGetSymbolAddress((void**)&vp,  g_v);
    cudaGetSymbolAddress((void**)&aop, g_ao);

    // 1/sqrt(64) * log2(e): softmax computed in exp2 domain
    const float scale = 0.125f * 1.4426950408889634f;

    dim3 gproj(NHD / 128, MROWS / 128);   // (8, 32)
    gemm_h<<<gproj, 256>>>(Q, Wq, bq, qp, MROWS, NHD, EMB, scale);
    gemm_h<<<gproj, 256>>>(K, Wk, bk, kp, MROWS, NHD, EMB, 1.0f);
    gemm_h<<<gproj, 256>>>(V, Wv, bv, vp, MROWS, NHD, EMB, 1.0f);

    dim3 gattn(SLEN / 128, NH, BS);       // (16, 16, 2)
    flash_h<<<gattn, 128>>>(qp, kp, vp, aop);

    dim3 gout(EMB / 128, MROWS / 128);    // (8, 32)
    gemm_h<<<gout, 256>>>(aop, Wo, bo, out, MROWS, EMB, NHD, 1.0f);
}

// round 6
// speedup vs baseline: 5.9386x; 1.0814x over previous
#include <cuda_runtime.h>
#include <cuda_fp16.h>
#include <stdint.h>

// Problem constants (fixed by the dataset)
#define BS    2
#define SLEN  2048
#define EMB   1024
#define NHD   1024   // NH*DM
#define NH    16
#define DM    64
#define MROWS (BS * SLEN)   // 4096

// ---------------- scratch (no allocation allowed) ----------------
__device__ __half g_q [MROWS * NHD];
__device__ __half g_k [MROWS * NHD];
__device__ __half g_v [MROWS * NHD];
__device__ __half g_ao[MROWS * NHD];

// ---------------- helpers ----------------
__device__ __forceinline__ uint32_t h2(float lo, float hi) {
    uint32_t r;
    asm("cvt.rn.f16x2.f32 %0, %1, %2;" : "=r"(r) : "f"(hi), "f"(lo));
    return r;
}
__device__ __forceinline__ float fexp2(float x) {
    float y;
    asm("ex2.approx.ftz.f32 %0, %1;" : "=f"(y) : "f"(x));
    return y;
}
// D += A(16x16) @ B(16x8), fp16 in, fp32 accum
__device__ __forceinline__ void mma16(float* d, const uint32_t* a, const uint32_t* b) {
    asm volatile(
        "mma.sync.aligned.m16n8k16.row.col.f32.f16.f16.f32 "
        "{%0,%1,%2,%3}, {%4,%5,%6,%7}, {%8,%9}, {%0,%1,%2,%3};"
        : "+f"(d[0]), "+f"(d[1]), "+f"(d[2]), "+f"(d[3])
        : "r"(a[0]), "r"(a[1]), "r"(a[2]), "r"(a[3]),
          "r"(b[0]), "r"(b[1]));
}
__device__ __forceinline__ void cp16(uint32_t saddr, const void* gptr) {
    asm volatile("cp.async.ca.shared.global [%0], [%1], 16;\n" :: "r"(saddr), "l"(gptr));
}
__device__ __forceinline__ uint32_t s2u(const void* p) {
    return (uint32_t)__cvta_generic_to_shared(p);
}
__device__ __forceinline__ void ldm_x4(uint32_t* r, uint32_t saddr) {
    asm volatile("ldmatrix.sync.aligned.m8n8.x4.shared.b16 {%0,%1,%2,%3}, [%4];"
        : "=r"(r[0]), "=r"(r[1]), "=r"(r[2]), "=r"(r[3]) : "r"(saddr));
}
__device__ __forceinline__ void ldm_x4t(uint32_t* r, uint32_t saddr) {
    asm volatile("ldmatrix.sync.aligned.m8n8.x4.trans.shared.b16 {%0,%1,%2,%3}, [%4];"
        : "=r"(r[0]), "=r"(r[1]), "=r"(r[2]), "=r"(r[3]) : "r"(saddr));
}

// ---------------- fp16 GEMM: C = alpha * (A[M,K] @ B[K,N] + bias[N]) ----------------
// BM=128, BN=128, BK=32, 256 threads (8 warps 2x4), warp tile 64x32.
// A: fp32 or fp16 (template). C: fp32 or fp16 (template). B/bias fp32.
#define AP 20    // As pitch in half2 words
#define BP 132   // Bs pitch in half2 words
#define ASZ (128 * AP)
#define BSZ (16 * BP)

template<typename AT, typename CT>
__global__ __launch_bounds__(256) void gemm_h(
    const AT* __restrict__ A, const float* __restrict__ B,
    const float* __restrict__ bias, CT* __restrict__ C,
    int M, int N, int K, float alpha)
{
    constexpr bool AH = (sizeof(AT) == 2);
    constexpr bool CH = (sizeof(CT) == 2);

    __shared__ uint32_t As[2 * ASZ];   // [m][kpair] half2
    __shared__ uint32_t Bs[2 * BSZ];   // [kpair][n] half2 {B[2k][n], B[2k+1][n]}

    const int tid  = threadIdx.x;
    const int lane = tid & 31;
    const int warp = tid >> 5;
    const int bm = blockIdx.y * 128;
    const int bn = blockIdx.x * 128;
    const int wm = (warp >> 2) * 64;
    const int wn = (warp & 3) * 32;
    const int qr = lane >> 2;
    const int qc = lane & 3;

    // fp32-A loader indices
    const int ar  = tid >> 3;
    const int ac  = (tid & 7) << 2;
    // fp16-A loader indices
    const int ahr = tid >> 2;          // 0..63 (+64)
    const int ahc = (tid & 3) << 3;    // half offset 0,8,16,24
    // B loader indices
    const int bpr = tid >> 5;
    const int bn4 = (tid & 31) << 2;

    float4 la[4];
    uint4  lah[2];
    float4 lb0[2], lb1[2];

    float acc[4][4][4];
    #pragma unroll
    for (int i = 0; i < 4; ++i)
        #pragma unroll
        for (int j = 0; j < 4; ++j)
            #pragma unroll
            for (int c = 0; c < 4; ++c) acc[i][j][c] = 0.f;

    auto ldg = [&](int k0) {
        if constexpr (AH) {
            #pragma unroll
            for (int r = 0; r < 2; ++r)
                lah[r] = *(const uint4*)((const __half*)A + (size_t)(bm + ahr + r * 64) * K + k0 + ahc);
        } else {
            #pragma unroll
            for (int r = 0; r < 4; ++r)
                la[r] = *(const float4*)((const float*)A + (size_t)(bm + ar + r * 32) * K + k0 + ac);
        }
        #pragma unroll
        for (int r = 0; r < 2; ++r) {
            int pr = bpr + r * 8;
            lb0[r] = *(const float4*)(B + (size_t)(k0 + 2 * pr)     * N + bn + bn4);
            lb1[r] = *(const float4*)(B + (size_t)(k0 + 2 * pr + 1) * N + bn + bn4);
        }
    };
    auto sts = [&](int s) {
        uint32_t* as = As + s * ASZ;
        uint32_t* bs = Bs + s * BSZ;
        if constexpr (AH) {
            #pragma unroll
            for (int r = 0; r < 2; ++r)
                *(uint4*)&as[(ahr + r * 64) * AP + (ahc >> 1)] = lah[r];
        } else {
            #pragma unroll
            for (int r = 0; r < 4; ++r) {
                uint2 u = make_uint2(h2(la[r].x, la[r].y), h2(la[r].z, la[r].w));
                *(uint2*)&as[(ar + r * 32) * AP + (ac >> 1)] = u;
            }
        }
        #pragma unroll
        for (int r = 0; r < 2; ++r) {
            int pr = bpr + r * 8;
            uint4 u = make_uint4(h2(lb0[r].x, lb1[r].x), h2(lb0[r].y, lb1[r].y),
                                 h2(lb0[r].z, lb1[r].z), h2(lb0[r].w, lb1[r].w));
            *(uint4*)&bs[pr * BP + bn4] = u;
        }
    };

    // ldmatrix A-fragment lane offset (words)
    const int mat  = lane >> 3;
    const int offa = ((mat & 1) * 8 + (lane & 7)) * AP + (mat >> 1) * 4;
    const uint32_t asb = s2u(As);

    const int nt = K >> 5;
    ldg(0); sts(0); __syncthreads();

    for (int it = 0; it < nt; ++it) {
        if (it + 1 < nt) ldg((it + 1) * 32);

        const uint32_t sbase = asb + ((it & 1) * ASZ) * 4;
        const uint32_t* bs = Bs + (it & 1) * BSZ;

        #pragma unroll
        for (int kb = 0; kb < 2; ++kb) {
            uint32_t af[4][4], bf[4][2];
            #pragma unroll
            for (int im = 0; im < 4; ++im)
                ldm_x4(af[im], sbase + ((wm + im * 16) * AP + kb * 8 + offa) * 4);
            #pragma unroll
            for (int in = 0; in < 4; ++in) {
                int n = wn + in * 8 + qr;
                bf[in][0] = bs[(kb * 8 + qc) * BP + n];
                bf[in][1] = bs[(kb * 8 + 4 + qc) * BP + n];
            }
            #pragma unroll
            for (int im = 0; im < 4; ++im)
                #pragma unroll
                for (int in = 0; in < 4; ++in)
                    mma16(acc[im][in], af[im], bf[in]);
        }

        if (it + 1 < nt) { sts((it + 1) & 1); __syncthreads(); }
    }

    // epilogue
    #pragma unroll
    for (int im = 0; im < 4; ++im) {
        #pragma unroll
        for (int in = 0; in < 4; ++in) {
            int row = bm + wm + im * 16 + qr;
            int col = bn + wn + in * 8 + qc * 2;
            float b0 = bias[col], b1 = bias[col + 1];
            float v00 = alpha * (acc[im][in][0] + b0);
            float v01 = alpha * (acc[im][in][1] + b1);
            float v10 = alpha * (acc[im][in][2] + b0);
            float v11 = alpha * (acc[im][in][3] + b1);
            if constexpr (CH) {
                *(uint32_t*)((__half*)C + (size_t)row * N + col)       = h2(v00, v01);
                *(uint32_t*)((__half*)C + (size_t)(row + 8) * N + col) = h2(v10, v11);
            } else {
                *(float2*)((float*)C + (size_t)row * N + col)       = make_float2(v00, v01);
                *(float2*)((float*)C + (size_t)(row + 8) * N + col) = make_float2(v10, v11);
            }
        }
    }
}

// ---------------- Flash attention: fp16, cp.async 3-stage, ldmatrix ----------------
// 128 threads (4 warps x 32 Q rows), 64-key tiles, online softmax in exp2 domain.
#define FQP 72   // row pitch in halves
#define FLASH_SMEM ((128 * FQP + 2 * 3 * 64 * FQP) * 2)   // 73728 B

__global__ __launch_bounds__(128) void flash_h(
    const __half* __restrict__ q, const __half* __restrict__ k,
    const __half* __restrict__ v, __half* __restrict__ o)
{
    extern __shared__ __half fsm[];
    __half* Qh = fsm;                       // [128][FQP]
    __half* Kh = Qh + 128 * FQP;            // 3 stages [64][FQP]
    __half* Vh = Kh + 3 * 64 * FQP;         // 3 stages [64][FQP]
    const uint32_t qb32 = s2u(Qh);
    const uint32_t kb32 = s2u(Kh);
    const uint32_t vb32 = s2u(Vh);

    const int tid  = threadIdx.x;
    const int lane = tid & 31;
    const int warp = tid >> 5;
    const int h = blockIdx.y, b = blockIdx.z;
    const int i0 = blockIdx.x * 128;
    const int m0 = warp * 32;
    const int qr = lane >> 2;
    const int qc = lane & 3;

    const size_t base = (size_t)b * SLEN * NHD + (size_t)h * DM;
    const __half* qg = q + base;
    const __half* kg = k + base;
    const __half* vg = v + base;
    __half*       og = o + base;

    // ---- async loaders ----
    auto issueKV = [&](int s, int t0) {
        uint32_t kd = kb32 + (s * 64 * FQP) * 2;
        uint32_t vd = vb32 + (s * 64 * FQP) * 2;
        #pragma unroll
        for (int rep = 0; rep < 4; ++rep) {
            int idx = rep * 128 + tid;
            int row = idx >> 3;
            int ch  = (idx & 7) << 3;       // halves
            cp16(kd + (row * FQP + ch) * 2, kg + (size_t)(t0 + row) * NHD + ch);
            cp16(vd + (row * FQP + ch) * 2, vg + (size_t)(t0 + row) * NHD + ch);
        }
        asm volatile("cp.async.commit_group;\n");
    };

    // prologue: Q + first two KV tiles
    #pragma unroll
    for (int rep = 0; rep < 8; ++rep) {
        int idx = rep * 128 + tid;
        int row = idx >> 3;
        int ch  = (idx & 7) << 3;
        cp16(qb32 + (row * FQP + ch) * 2, qg + (size_t)(i0 + row) * NHD + ch);
    }
    asm volatile("cp.async.commit_group;\n");
    issueKV(0, 0);
    issueKV(1, 64);
    asm volatile("cp.async.wait_group 2;\n");
    __syncthreads();

    // ldmatrix lane offsets (in halves)
    const int mat  = lane >> 3;
    const int offq = ((mat & 1) * 8 + (lane & 7)) * FQP + (mat >> 1) * 8;  // A frags (Q)
    const int offk = ((mat >> 1) * 8 + (lane & 7)) * FQP + (mat & 1) * 8;  // B frags (K)
    const int offv = ((mat & 1) * 8 + (lane & 7)) * FQP + (mat >> 1) * 8;  // B frags (V, trans)

    // hoist Q fragments into registers (reused by all 32 tiles)
    uint32_t qf[2][4][4];
    #pragma unroll
    for (int im = 0; im < 2; ++im)
        #pragma unroll
        for (int kd = 0; kd < 4; ++kd)
            ldm_x4(qf[im][kd], qb32 + ((m0 + im * 16) * FQP + kd * 16 + offq) * 2);

    float ofrag[2][8][4];
    #pragma unroll
    for (int im = 0; im < 2; ++im)
        #pragma unroll
        for (int t = 0; t < 8; ++t)
            #pragma unroll
            for (int c = 0; c < 4; ++c) ofrag[im][t][c] = 0.f;
    float mrow[4] = {-1e30f, -1e30f, -1e30f, -1e30f};
    float lrow[4] = {0.f, 0.f, 0.f, 0.f};

    const int nt = SLEN / 64;   // 32
    for (int it = 0; it < nt; ++it) {
        if (it + 1 < nt) { asm volatile("cp.async.wait_group 1;\n"); }
        else             { asm volatile("cp.async.wait_group 0;\n"); }
        __syncthreads();

        const uint32_t ks32 = kb32 + ((it % 3) * 64 * FQP) * 2;
        const uint32_t vs32 = vb32 + ((it % 3) * 64 * FQP) * 2;

        // ---- S = Q @ K^T ----
        float sfrag[2][8][4];
        #pragma unroll
        for (int im = 0; im < 2; ++im)
            #pragma unroll
            for (int t = 0; t < 8; ++t)
                #pragma unroll
                for (int c = 0; c < 4; ++c) sfrag[im][t][c] = 0.f;

        #pragma unroll
        for (int kd = 0; kd < 4; ++kd) {
            uint32_t bf[8][2];
            #pragma unroll
            for (int tp = 0; tp < 4; ++tp) {
                uint32_t r[4];
                ldm_x4(r, ks32 + (tp * 16 * FQP + kd * 16 + offk) * 2);
                bf[2*tp][0] = r[0]; bf[2*tp][1] = r[1];
                bf[2*tp+1][0] = r[2]; bf[2*tp+1][1] = r[3];
            }
            #pragma unroll
            for (int t = 0; t < 8; ++t) {
                mma16(sfrag[0][t], qf[0][kd], bf[t]);
                mma16(sfrag[1][t], qf[1][kd], bf[t]);
            }
        }

        // ---- online softmax (exp2 domain) ----
        #pragma unroll
        for (int im = 0; im < 2; ++im) {
            #pragma unroll
            for (int hh = 0; hh < 2; ++hh) {
                const int s = im * 2 + hh;
                float mx = -1e30f;
                #pragma unroll
                for (int t = 0; t < 8; ++t)
                    mx = fmaxf(mx, fmaxf(sfrag[im][t][2*hh], sfrag[im][t][2*hh + 1]));
                mx = fmaxf(mx, __shfl_xor_sync(0xffffffffu, mx, 1));
                mx = fmaxf(mx, __shfl_xor_sync(0xffffffffu, mx, 2));
                float mnew = fmaxf(mrow[s], mx);
                float corr = fexp2(mrow[s] - mnew);
                float sum = 0.f;
                #pragma unroll
                for (int t = 0; t < 8; ++t) {
                    float e0 = fexp2(sfrag[im][t][2*hh]     - mnew);
                    float e1 = fexp2(sfrag[im][t][2*hh + 1] - mnew);
                    sfrag[im][t][2*hh] = e0; sfrag[im][t][2*hh + 1] = e1;
                    sum += e0 + e1;
                }
                sum += __shfl_xor_sync(0xffffffffu, sum, 1);
                sum += __shfl_xor_sync(0xffffffffu, sum, 2);
                lrow[s] = lrow[s] * corr + sum;
                mrow[s] = mnew;
                #pragma unroll
                for (int t = 0; t < 8; ++t) {
                    ofrag[im][t][2*hh]     *= corr;
                    ofrag[im][t][2*hh + 1] *= corr;
                }
            }
        }

        // ---- pack P: C-frag -> A-frag in registers ----
        uint32_t p01[2][8], p23[2][8];
        #pragma unroll
        for (int im = 0; im < 2; ++im)
            #pragma unroll
            for (int t = 0; t < 8; ++t) {
                p01[im][t] = h2(sfrag[im][t][0], sfrag[im][t][1]);
                p23[im][t] = h2(sfrag[im][t][2], sfrag[im][t][3]);
            }

        // ---- O += P @ V ----
        #pragma unroll
        for (int g = 0; g < 4; ++g) {
            uint32_t bv[8][2];
            #pragma unroll
            for (int tp = 0; tp < 4; ++tp) {
                uint32_t r[4];
                ldm_x4t(r, vs32 + (g * 16 * FQP + tp * 16 + offv) * 2);
                bv[2*tp][0] = r[0]; bv[2*tp][1] = r[1];
                bv[2*tp+1][0] = r[2]; bv[2*tp+1][1] = r[3];
            }
            uint32_t a0[4] = { p01[0][2*g], p23[0][2*g], p01[0][2*g+1], p23[0][2*g+1] };
            uint32_t a1[4] = { p01[1][2*g], p23[1][2*g], p01[1][2*g+1], p23[1][2*g+1] };
            #pragma unroll
            for (int t = 0; t < 8; ++t) {
                mma16(ofrag[0][t], a0, bv[t]);
                mma16(ofrag[1][t], a1, bv[t]);
            }
        }

        if (it + 2 < nt) issueKV((it + 2) % 3, (it + 2) * 64);
    }

    // ---- normalize, store O (fp16) ----
    #pragma unroll
    for (int im = 0; im < 2; ++im) {
        float inv0 = 1.f / lrow[im * 2];
        float inv1 = 1.f / lrow[im * 2 + 1];
        int r = i0 + m0 + im * 16 + qr;
        #pragma unroll
        for (int t = 0; t < 8; ++t) {
            int col = t * 8 + qc * 2;
            *(uint32_t*)(og + (size_t)r * NHD + col) =
                h2(ofrag[im][t][0] * inv0, ofrag[im][t][1] * inv0);
            *(uint32_t*)(og + (size_t)(r + 8) * NHD + col) =
                h2(ofrag[im][t][2] * inv1, ofrag[im][t][3] * inv1);
        }
    }
}

// ---------------- launch ----------------
extern "C" void kernel_launch(void* const* d_in, const int* in_sizes, int n_in,
                              void* d_out, int out_size)
{
    const float* Q  = (const float*)d_in[0];
    const float* K  = (const float*)d_in[1];
    const float* V  = (const float*)d_in[2];
    const float* Wq = (const float*)d_in[3];
    const float* bq = (const float*)d_in[4];
    const float* Wk = (const float*)d_in[5];
    const float* bk = (const float*)d_in[6];
    const float* Wv = (const float*)d_in[7];
    const float* bv = (const float*)d_in[8];
    const float* Wo = (const float*)d_in[9];
    const float* bo = (const float*)d_in[10];
    float* out = (float*)d_out;

    __half *qp, *kp, *vp, *aop;
    cudaGetSymbolAddress((void**)&qp,  g_q);
    cudaGetSymbolAddress((void**)&kp,  g_k);
    cudaGetSymbolAddress((void**)&vp,  g_v);
    cudaGetSymbolAddress((void**)&aop, g_ao);

    // 1/sqrt(64) * log2(e): softmax computed in exp2 domain
    const float scale = 0.125f * 1.4426950408889634f;

    cudaFuncSetAttribute(flash_h, cudaFuncAttributeMaxDynamicSharedMemorySize, FLASH_SMEM);

    dim3 gproj(NHD / 128, MROWS / 128);   // (8, 32)
    gemm_h<float, __half><<<gproj, 256>>>(Q, Wq, bq, qp, MROWS, NHD, EMB, scale);
    gemm_h<float, __half><<<gproj, 256>>>(K, Wk, bk, kp, MROWS, NHD, EMB, 1.0f);
    gemm_h<float, __half><<<gproj, 256>>>(V, Wv, bv, vp, MROWS, NHD, EMB, 1.0f);

    dim3 gattn(SLEN / 128, NH, BS);       // (16, 16, 2)
    flash_h<<<gattn, 128, FLASH_SMEM>>>(qp, kp, vp, aop);

    dim3 gout(EMB / 128, MROWS / 128);    // (8, 32)
    gemm_h<__half, float><<<gout, 256>>>(aop, Wo, bo, out, MROWS, EMB, NHD, 1.0f);
}

// round 7
// speedup vs baseline: 7.8324x; 1.3189x over previous
#include <cuda_runtime.h>
#include <cuda_fp16.h>
#include <stdint.h>

// Problem constants (fixed by the dataset)
#define BS    2
#define SLEN  2048
#define EMB   1024
#define NHD   1024   // NH*DM
#define NH    16
#define DM    64
#define MROWS (BS * SLEN)   // 4096

// ---------------- scratch (no allocation allowed) ----------------
__device__ __half g_qi[MROWS * EMB];   // fp16 copies of inputs
__device__ __half g_ki[MROWS * EMB];
__device__ __half g_vi[MROWS * EMB];
__device__ __half g_wq[EMB * NHD];     // fp16 copies of weights
__device__ __half g_wk[EMB * NHD];
__device__ __half g_wv[EMB * NHD];
__device__ __half g_wo[NHD * EMB];
__device__ __half g_q [MROWS * NHD];   // projected q/k/v, attention out
__device__ __half g_k [MROWS * NHD];
__device__ __half g_v [MROWS * NHD];
__device__ __half g_ao[MROWS * NHD];

// ---------------- helpers ----------------
__device__ __forceinline__ uint32_t h2(float lo, float hi) {
    uint32_t r;
    asm("cvt.rn.f16x2.f32 %0, %1, %2;" : "=r"(r) : "f"(hi), "f"(lo));
    return r;
}
__device__ __forceinline__ float fexp2(float x) {
    float y;
    asm("ex2.approx.ftz.f32 %0, %1;" : "=f"(y) : "f"(x));
    return y;
}
__device__ __forceinline__ void mma16(float* d, const uint32_t* a, const uint32_t* b) {
    asm volatile(
        "mma.sync.aligned.m16n8k16.row.col.f32.f16.f16.f32 "
        "{%0,%1,%2,%3}, {%4,%5,%6,%7}, {%8,%9}, {%0,%1,%2,%3};"
        : "+f"(d[0]), "+f"(d[1]), "+f"(d[2]), "+f"(d[3])
        : "r"(a[0]), "r"(a[1]), "r"(a[2]), "r"(a[3]),
          "r"(b[0]), "r"(b[1]));
}
__device__ __forceinline__ void cp16(uint32_t saddr, const void* gptr) {
    asm volatile("cp.async.ca.shared.global [%0], [%1], 16;\n" :: "r"(saddr), "l"(gptr));
}
__device__ __forceinline__ uint32_t s2u(const void* p) {
    return (uint32_t)__cvta_generic_to_shared(p);
}
__device__ __forceinline__ void ldm_x4(uint32_t* r, uint32_t saddr) {
    asm volatile("ldmatrix.sync.aligned.m8n8.x4.shared.b16 {%0,%1,%2,%3}, [%4];"
        : "=r"(r[0]), "=r"(r[1]), "=r"(r[2]), "=r"(r[3]) : "r"(saddr));
}
__device__ __forceinline__ void ldm_x4t(uint32_t* r, uint32_t saddr) {
    asm volatile("ldmatrix.sync.aligned.m8n8.x4.trans.shared.b16 {%0,%1,%2,%3}, [%4];"
        : "=r"(r[0]), "=r"(r[1]), "=r"(r[2]), "=r"(r[3]) : "r"(saddr));
}

// ---------------- fp32 -> fp16 conversion kernels ----------------
__global__ __launch_bounds__(256) void cvt3(
    const float4* __restrict__ a, const float4* __restrict__ b,
    const float4* __restrict__ c, int n4)
{
    const float4* in = (blockIdx.y == 0) ? a : (blockIdx.y == 1) ? b : c;
    __half* out = (blockIdx.y == 0) ? g_qi : (blockIdx.y == 1) ? g_ki : g_vi;
    int i = blockIdx.x * 256 + threadIdx.x;
    if (i < n4) {
        float4 t = in[i];
        *(uint2*)(out + 4 * (size_t)i) = make_uint2(h2(t.x, t.y), h2(t.z, t.w));
    }
}
__global__ __launch_bounds__(256) void cvt4(
    const float4* __restrict__ a, const float4* __restrict__ b,
    const float4* __restrict__ c, const float4* __restrict__ d, int n4)
{
    const float4* in = (blockIdx.y == 0) ? a : (blockIdx.y == 1) ? b :
                       (blockIdx.y == 2) ? c : d;
    __half* out = (blockIdx.y == 0) ? g_wq : (blockIdx.y == 1) ? g_wk :
                  (blockIdx.y == 2) ? g_wv : g_wo;
    int i = blockIdx.x * 256 + threadIdx.x;
    if (i < n4) {
        float4 t = in[i];
        *(uint2*)(out + 4 * (size_t)i) = make_uint2(h2(t.x, t.y), h2(t.z, t.w));
    }
}

// ---------------- fp16 GEMM v2: C = alpha * (A[M,K] @ B[K,N] + bias[N]) ----------------
// BM=128, BN=256, BK=32, 256 threads (8 warps 2x4), warp tile 64x64.
// 3-stage cp.async, 1 sync per k-tile, ldmatrix A + ldmatrix.trans B.
#define APh 40    // As pitch in halves (20 words: conflict-free ldmatrix)
#define BPh 264   // Bs pitch in halves (132 words: conflict-free ldmatrix)
#define A_ST (128 * APh)
#define B_ST (32 * BPh)
#define GEMM_SMEM ((3 * (A_ST + B_ST)) * 2)   // 81408 B

template<typename CT>
__global__ __launch_bounds__(256) void gemm_h16(
    const __half* __restrict__ A, const __half* __restrict__ B,
    const float* __restrict__ bias, CT* __restrict__ C,
    int M, int N, int K, float alpha)
{
    constexpr bool CH = (sizeof(CT) == 2);
    extern __shared__ __half gsm[];
    __half* Ash = gsm;
    __half* Bsh = gsm + 3 * A_ST;
    const uint32_t ab = s2u(Ash);
    const uint32_t bb = s2u(Bsh);

    const int tid  = threadIdx.x;
    const int lane = tid & 31;
    const int warp = tid >> 5;
    const int bm = blockIdx.y * 128;
    const int bn = blockIdx.x * 256;
    const int wm = (warp >> 2) * 64;
    const int wn = (warp & 3) * 64;
    const int qr = lane >> 2;
    const int qc = lane & 3;

    float acc[4][8][4];
    #pragma unroll
    for (int i = 0; i < 4; ++i)
        #pragma unroll
        for (int j = 0; j < 8; ++j)
            #pragma unroll
            for (int c = 0; c < 4; ++c) acc[i][j][c] = 0.f;

    auto issue = [&](int s, int k0) {
        uint32_t ad = ab + (s * A_ST) * 2;
        uint32_t bd = bb + (s * B_ST) * 2;
        #pragma unroll
        for (int rep = 0; rep < 2; ++rep) {      // A: 128 rows x 32 halves
            int idx = rep * 256 + tid;
            int row = idx >> 2;
            int ch  = (idx & 3) << 3;
            cp16(ad + (row * APh + ch) * 2, A + (size_t)(bm + row) * K + k0 + ch);
        }
        #pragma unroll
        for (int rep = 0; rep < 4; ++rep) {      // B: 32 rows x 256 halves
            int idx = rep * 256 + tid;
            int row = idx >> 5;
            int ch  = (idx & 31) << 3;
            cp16(bd + (row * BPh + ch) * 2, B + (size_t)(k0 + row) * N + bn + ch);
        }
        asm volatile("cp.async.commit_group;\n");
    };

    // ldmatrix lane offsets (halves)
    const int mat  = lane >> 3;
    const int offA = ((mat & 1) * 8 + (lane & 7)) * APh + (mat >> 1) * 8;
    const int offB = ((mat & 1) * 8 + (lane & 7)) * BPh + (mat >> 1) * 8;

    const int nt = K >> 5;   // 32
    issue(0, 0);
    issue(1, 32);

    for (int it = 0; it < nt; ++it) {
        if (it + 1 < nt) { asm volatile("cp.async.wait_group 1;\n"); }
        else             { asm volatile("cp.async.wait_group 0;\n"); }
        __syncthreads();
        if (it + 2 < nt) issue((it + 2) % 3, (it + 2) * 32);

        const uint32_t as = ab + ((it % 3) * A_ST) * 2;
        const uint32_t bs = bb + ((it % 3) * B_ST) * 2;

        #pragma unroll
        for (int kb = 0; kb < 2; ++kb) {
            uint32_t af[4][4], bf[8][2];
            #pragma unroll
            for (int im = 0; im < 4; ++im)
                ldm_x4(af[im], as + ((wm + im * 16) * APh + kb * 16 + offA) * 2);
            #pragma unroll
            for (int np = 0; np < 4; ++np) {
                uint32_t r[4];
                ldm_x4t(r, bs + ((kb * 16) * BPh + wn + np * 16 + offB) * 2);
                bf[2*np][0] = r[0]; bf[2*np][1] = r[1];
                bf[2*np+1][0] = r[2]; bf[2*np+1][1] = r[3];
            }
            #pragma unroll
            for (int im = 0; im < 4; ++im)
                #pragma unroll
                for (int in = 0; in < 8; ++in)
                    mma16(acc[im][in], af[im], bf[in]);
        }
    }

    // epilogue
    #pragma unroll
    for (int im = 0; im < 4; ++im) {
        #pragma unroll
        for (int in = 0; in < 8; ++in) {
            int row = bm + wm + im * 16 + qr;
            int col = bn + wn + in * 8 + qc * 2;
            float b0 = bias[col], b1 = bias[col + 1];
            float v00 = alpha * (acc[im][in][0] + b0);
            float v01 = alpha * (acc[im][in][1] + b1);
            float v10 = alpha * (acc[im][in][2] + b0);
            float v11 = alpha * (acc[im][in][3] + b1);
            if constexpr (CH) {
                *(uint32_t*)((__half*)C + (size_t)row * N + col)       = h2(v00, v01);
                *(uint32_t*)((__half*)C + (size_t)(row + 8) * N + col) = h2(v10, v11);
            } else {
                *(float2*)((float*)C + (size_t)row * N + col)       = make_float2(v00, v01);
                *(float2*)((float*)C + (size_t)(row + 8) * N + col) = make_float2(v10, v11);
            }
        }
    }
}

// ---------------- Flash attention: fp16, cp.async 3-stage, ldmatrix ----------------
#define FQP 72   // row pitch in halves
#define FLASH_SMEM ((128 * FQP + 2 * 3 * 64 * FQP) * 2)   // 73728 B

__global__ __launch_bounds__(128) void flash_h(
    const __half* __restrict__ q, const __half* __restrict__ k,
    const __half* __restrict__ v, __half* __restrict__ o)
{
    extern __shared__ __half fsm[];
    __half* Qh = fsm;
    __half* Kh = Qh + 128 * FQP;
    __half* Vh = Kh + 3 * 64 * FQP;
    const uint32_t qb32 = s2u(Qh);
    const uint32_t kb32 = s2u(Kh);
    const uint32_t vb32 = s2u(Vh);

    const int tid  = threadIdx.x;
    const int lane = tid & 31;
    const int warp = tid >> 5;
    const int h = blockIdx.y, b = blockIdx.z;
    const int i0 = blockIdx.x * 128;
    const int m0 = warp * 32;
    const int qr = lane >> 2;
    const int qc = lane & 3;

    const size_t base = (size_t)b * SLEN * NHD + (size_t)h * DM;
    const __half* qg = q + base;
    const __half* kg = k + base;
    const __half* vg = v + base;
    __half*       og = o + base;

    auto issueKV = [&](int s, int t0) {
        uint32_t kd = kb32 + (s * 64 * FQP) * 2;
        uint32_t vd = vb32 + (s * 64 * FQP) * 2;
        #pragma unroll
        for (int rep = 0; rep < 4; ++rep) {
            int idx = rep * 128 + tid;
            int row = idx >> 3;
            int ch  = (idx & 7) << 3;
            cp16(kd + (row * FQP + ch) * 2, kg + (size_t)(t0 + row) * NHD + ch);
            cp16(vd + (row * FQP + ch) * 2, vg + (size_t)(t0 + row) * NHD + ch);
        }
        asm volatile("cp.async.commit_group;\n");
    };

    #pragma unroll
    for (int rep = 0; rep < 8; ++rep) {
        int idx = rep * 128 + tid;
        int row = idx >> 3;
        int ch  = (idx & 7) << 3;
        cp16(qb32 + (row * FQP + ch) * 2, qg + (size_t)(i0 + row) * NHD + ch);
    }
    asm volatile("cp.async.commit_group;\n");
    issueKV(0, 0);
    issueKV(1, 64);
    asm volatile("cp.async.wait_group 2;\n");
    __syncthreads();

    const int mat  = lane >> 3;
    const int offq = ((mat & 1) * 8 + (lane & 7)) * FQP + (mat >> 1) * 8;
    const int offk = ((mat >> 1) * 8 + (lane & 7)) * FQP + (mat & 1) * 8;
    const int offv = ((mat & 1) * 8 + (lane & 7)) * FQP + (mat >> 1) * 8;

    uint32_t qf[2][4][4];
    #pragma unroll
    for (int im = 0; im < 2; ++im)
        #pragma unroll
        for (int kd = 0; kd < 4; ++kd)
            ldm_x4(qf[im][kd], qb32 + ((m0 + im * 16) * FQP + kd * 16 + offq) * 2);

    float ofrag[2][8][4];
    #pragma unroll
    for (int im = 0; im < 2; ++im)
        #pragma unroll
        for (int t = 0; t < 8; ++t)
            #pragma unroll
            for (int c = 0; c < 4; ++c) ofrag[im][t][c] = 0.f;
    float mrow[4] = {-1e30f, -1e30f, -1e30f, -1e30f};
    float lrow[4] = {0.f, 0.f, 0.f, 0.f};

    const int nt = SLEN / 64;
    for (int it = 0; it < nt; ++it) {
        if (it + 1 < nt) { asm volatile("cp.async.wait_group 1;\n"); }
        else             { asm volatile("cp.async.wait_group 0;\n"); }
        __syncthreads();
        if (it + 2 < nt) issueKV((it + 2) % 3, (it + 2) * 64);

        const uint32_t ks32 = kb32 + ((it % 3) * 64 * FQP) * 2;
        const uint32_t vs32 = vb32 + ((it % 3) * 64 * FQP) * 2;

        float sfrag[2][8][4];
        #pragma unroll
        for (int im = 0; im < 2; ++im)
            #pragma unroll
            for (int t = 0; t < 8; ++t)
                #pragma unroll
                for (int c = 0; c < 4; ++c) sfrag[im][t][c] = 0.f;

        #pragma unroll
        for (int kd = 0; kd < 4; ++kd) {
            uint32_t bf[8][2];
            #pragma unroll
            for (int tp = 0; tp < 4; ++tp) {
                uint32_t r[4];
                ldm_x4(r, ks32 + (tp * 16 * FQP + kd * 16 + offk) * 2);
                bf[2*tp][0] = r[0]; bf[2*tp][1] = r[1];
                bf[2*tp+1][0] = r[2]; bf[2*tp+1][1] = r[3];
            }
            #pragma unroll
            for (int t = 0; t < 8; ++t) {
                mma16(sfrag[0][t], qf[0][kd], bf[t]);
                mma16(sfrag[1][t], qf[1][kd], bf[t]);
            }
        }

        #pragma unroll
        for (int im = 0; im < 2; ++im) {
            #pragma unroll
            for (int hh = 0; hh < 2; ++hh) {
                const int s = im * 2 + hh;
                float mx = -1e30f;
                #pragma unroll
                for (int t = 0; t < 8; ++t)
                    mx = fmaxf(mx, fmaxf(sfrag[im][t][2*hh], sfrag[im][t][2*hh + 1]));
                mx = fmaxf(mx, __shfl_xor_sync(0xffffffffu, mx, 1));
                mx = fmaxf(mx, __shfl_xor_sync(0xffffffffu, mx, 2));
                float mnew = fmaxf(mrow[s], mx);
                float corr = fexp2(mrow[s] - mnew);
                float sum = 0.f;
                #pragma unroll
                for (int t = 0; t < 8; ++t) {
                    float e0 = fexp2(sfrag[im][t][2*hh]     - mnew);
                    float e1 = fexp2(sfrag[im][t][2*hh + 1] - mnew);
                    sfrag[im][t][2*hh] = e0; sfrag[im][t][2*hh + 1] = e1;
                    sum += e0 + e1;
                }
                sum += __shfl_xor_sync(0xffffffffu, sum, 1);
                sum += __shfl_xor_sync(0xffffffffu, sum, 2);
                lrow[s] = lrow[s] * corr + sum;
                mrow[s] = mnew;
                #pragma unroll
                for (int t = 0; t < 8; ++t) {
                    ofrag[im][t][2*hh]     *= corr;
                    ofrag[im][t][2*hh + 1] *= corr;
                }
            }
        }

        uint32_t p01[2][8], p23[2][8];
        #pragma unroll
        for (int im = 0; im < 2; ++im)
            #pragma unroll
            for (int t = 0; t < 8; ++t) {
                p01[im][t] = h2(sfrag[im][t][0], sfrag[im][t][1]);
                p23[im][t] = h2(sfrag[im][t][2], sfrag[im][t][3]);
            }

        #pragma unroll
        for (int g = 0; g < 4; ++g) {
            uint32_t bv[8][2];
            #pragma unroll
            for (int tp = 0; tp < 4; ++tp) {
                uint32_t r[4];
                ldm_x4t(r, vs32 + (g * 16 * FQP + tp * 16 + offv) * 2);
                bv[2*tp][0] = r[0]; bv[2*tp][1] = r[1];
                bv[2*tp+1][0] = r[2]; bv[2*tp+1][1] = r[3];
            }
            uint32_t a0[4] = { p01[0][2*g], p23[0][2*g], p01[0][2*g+1], p23[0][2*g+1] };
            uint32_t a1[4] = { p01[1][2*g], p23[1][2*g], p01[1][2*g+1], p23[1][2*g+1] };
            #pragma unroll
            for (int t = 0; t < 8; ++t) {
                mma16(ofrag[0][t], a0, bv[t]);
                mma16(ofrag[1][t], a1, bv[t]);
            }
        }
    }

    #pragma unroll
    for (int im = 0; im < 2; ++im) {
        float inv0 = 1.f / lrow[im * 2];
        float inv1 = 1.f / lrow[im * 2 + 1];
        int r = i0 + m0 + im * 16 + qr;
        #pragma unroll
        for (int t = 0; t < 8; ++t) {
            int col = t * 8 + qc * 2;
            *(uint32_t*)(og + (size_t)r * NHD + col) =
                h2(ofrag[im][t][0] * inv0, ofrag[im][t][1] * inv0);
            *(uint32_t*)(og + (size_t)(r + 8) * NHD + col) =
                h2(ofrag[im][t][2] * inv1, ofrag[im][t][3] * inv1);
        }
    }
}

// ---------------- launch ----------------
extern "C" void kernel_launch(void* const* d_in, const int* in_sizes, int n_in,
                              void* d_out, int out_size)
{
    const float* Q  = (const float*)d_in[0];
    const float* K  = (const float*)d_in[1];
    const float* V  = (const float*)d_in[2];
    const float* Wq = (const float*)d_in[3];
    const float* bq = (const float*)d_in[4];
    const float* Wk = (const float*)d_in[5];
    const float* bk = (const float*)d_in[6];
    const float* Wv = (const float*)d_in[7];
    const float* bv = (const float*)d_in[8];
    const float* Wo = (const float*)d_in[9];
    const float* bo = (const float*)d_in[10];
    float* out = (float*)d_out;

    __half *qip, *kip, *vip, *wqp, *wkp, *wvp, *wop, *qp, *kp, *vp, *aop;
    cudaGetSymbolAddress((void**)&qip, g_qi);
    cudaGetSymbolAddress((void**)&kip, g_ki);
    cudaGetSymbolAddress((void**)&vip, g_vi);
    cudaGetSymbolAddress((void**)&wqp, g_wq);
    cudaGetSymbolAddress((void**)&wkp, g_wk);
    cudaGetSymbolAddress((void**)&wvp, g_wv);
    cudaGetSymbolAddress((void**)&wop, g_wo);
    cudaGetSymbolAddress((void**)&qp,  g_q);
    cudaGetSymbolAddress((void**)&kp,  g_k);
    cudaGetSymbolAddress((void**)&vp,  g_v);
    cudaGetSymbolAddress((void**)&aop, g_ao);

    const float scale = 0.125f * 1.4426950408889634f;  // 1/sqrt(64) * log2(e)

    cudaFuncSetAttribute(flash_h, cudaFuncAttributeMaxDynamicSharedMemorySize, FLASH_SMEM);
    cudaFuncSetAttribute(gemm_h16<__half>, cudaFuncAttributeMaxDynamicSharedMemorySize, GEMM_SMEM);
    cudaFuncSetAttribute(gemm_h16<float>,  cudaFuncAttributeMaxDynamicSharedMemorySize, GEMM_SMEM);

    // fp32 -> fp16 conversions (inputs + weights)
    {
        int n4i = MROWS * EMB / 4;      // 1048576
        dim3 g3((n4i + 255) / 256, 3);
        cvt3<<<g3, 256>>>((const float4*)Q, (const float4*)K, (const float4*)V, n4i);
        int n4w = EMB * NHD / 4;        // 262144
        dim3 g4((n4w + 255) / 256, 4);
        cvt4<<<g4, 256>>>((const float4*)Wq, (const float4*)Wk,
                          (const float4*)Wv, (const float4*)Wo, n4w);
    }

    dim3 gproj(NHD / 256, MROWS / 128);   // (4, 32)
    gemm_h16<__half><<<gproj, 256, GEMM_SMEM>>>(qip, wqp, bq, qp, MROWS, NHD, EMB, scale);
    gemm_h16<__half><<<gproj, 256, GEMM_SMEM>>>(kip, wkp, bk, kp, MROWS, NHD, EMB, 1.0f);
    gemm_h16<__half><<<gproj, 256, GEMM_SMEM>>>(vip, wvp, bv, vp, MROWS, NHD, EMB, 1.0f);

    dim3 gattn(SLEN / 128, NH, BS);       // (16, 16, 2)
    flash_h<<<gattn, 128, FLASH_SMEM>>>(qp, kp, vp, aop);

    dim3 gout(EMB / 256, MROWS / 128);    // (4, 32)
    gemm_h16<float><<<gout, 256, GEMM_SMEM>>>(aop, wop, bo, out, MROWS, EMB, NHD, 1.0f);
}